// round 1
// baseline (speedup 1.0000x reference)
#include <cuda_runtime.h>
#include <cuda_bf16.h>
#include <cstddef>

// ---------------- problem constants ----------------
#define MAXN 50000
#define MAXE 400000
#define MAXTE (MAXN + MAXE)
#define HC1 256   // H*HID layer1
#define C2  64    // OUT layer2

// ---------------- device scratch ----------------
__device__ float    g_xl1[(size_t)MAXN * HC1];
__device__ float    g_xr1[(size_t)MAXN * HC1];
__device__ float    g_agg[(size_t)MAXN * HC1];   // layer1 aggregate, then elu'd h in place
__device__ float    g_xl2[(size_t)MAXN * C2];
__device__ float    g_xr2[(size_t)MAXN * C2];
__device__ float    g_ebuf[(size_t)MAXTE * 4];   // logits -> exp values (in place)
__device__ unsigned g_emax[(size_t)MAXN * 4];    // encoded float max
__device__ float    g_denom[(size_t)MAXN * 4];

// monotone float<->uint encoding so unsigned atomicMax == float max
__device__ __forceinline__ unsigned fenc(float f) {
    unsigned u = __float_as_uint(f);
    return (u & 0x80000000u) ? ~u : (u | 0x80000000u);
}
__device__ __forceinline__ float fdec(unsigned u) {
    return (u & 0x80000000u) ? __uint_as_float(u & 0x7fffffffu)
                             : __uint_as_float(~u);
}

// ---------------- zero fill ----------------
__global__ void zerof(float* p, int n) {
    int i = blockIdx.x * blockDim.x + threadIdx.x;
    if (i < n) p[i] = 0.0f;
}

// ---------------- SGEMM: C = A[MxK] @ B[KxNc] + bias, fp32 ----------------
// 128x128 tile, BK=8, 256 threads, 8x8 per thread.
__global__ __launch_bounds__(256, 2)
void gemm_bias(const float* __restrict__ A, const float* __restrict__ B,
               const float* __restrict__ bias, float* __restrict__ C,
               int M, int K, int Nc) {
    __shared__ float As[8][128];
    __shared__ float Bs[8][128];
    const int tid  = threadIdx.x;
    const int row0 = blockIdx.y * 128;
    const int col0 = blockIdx.x * 128;
    const int tx = tid & 15, ty = tid >> 4;

    float acc[8][8];
#pragma unroll
    for (int i = 0; i < 8; ++i)
#pragma unroll
        for (int j = 0; j < 8; ++j) acc[i][j] = 0.0f;

    const int arow  = tid >> 1;        // 0..127
    const int acol4 = (tid & 1) * 4;   // 0 or 4

    for (int k0 = 0; k0 < K; k0 += 8) {
        // load A tile (128 x 8), transposed into As[k][m]
        if (row0 + arow < M) {
            float4 v = *(const float4*)(A + (size_t)(row0 + arow) * K + k0 + acol4);
            As[acol4 + 0][arow] = v.x;
            As[acol4 + 1][arow] = v.y;
            As[acol4 + 2][arow] = v.z;
            As[acol4 + 3][arow] = v.w;
        } else {
            As[acol4 + 0][arow] = 0.f;
            As[acol4 + 1][arow] = 0.f;
            As[acol4 + 2][arow] = 0.f;
            As[acol4 + 3][arow] = 0.f;
        }
        // load B tile (8 x 128)
#pragma unroll
        for (int i = 0; i < 4; ++i) {
            int lin = tid + i * 256;
            int kk = lin >> 7, n = lin & 127;
            float v = 0.f;
            if (col0 + n < Nc) v = B[(size_t)(k0 + kk) * Nc + col0 + n];
            Bs[kk][n] = v;
        }
        __syncthreads();
#pragma unroll
        for (int kk = 0; kk < 8; ++kk) {
            float4 a0 = *(const float4*)&As[kk][ty * 8];
            float4 a1 = *(const float4*)&As[kk][ty * 8 + 4];
            float4 b0 = *(const float4*)&Bs[kk][tx * 8];
            float4 b1 = *(const float4*)&Bs[kk][tx * 8 + 4];
            float a[8] = {a0.x, a0.y, a0.z, a0.w, a1.x, a1.y, a1.z, a1.w};
            float b[8] = {b0.x, b0.y, b0.z, b0.w, b1.x, b1.y, b1.z, b1.w};
#pragma unroll
            for (int i = 0; i < 8; ++i)
#pragma unroll
                for (int j = 0; j < 8; ++j) acc[i][j] += a[i] * b[j];
        }
        __syncthreads();
    }

#pragma unroll
    for (int i = 0; i < 8; ++i) {
        int r = row0 + ty * 8 + i;
        if (r >= M) continue;
#pragma unroll
        for (int j = 0; j < 8; ++j) {
            int c = col0 + tx * 8 + j;
            if (c < Nc) C[(size_t)r * Nc + c] = acc[i][j] + __ldg(bias + c);
        }
    }
}

// ---------------- edge: attention logits + segment max ----------------
template <int H, int C>
__global__ void edge_scores(const int* __restrict__ ei, int E, int TE,
                            const float* __restrict__ xl, const float* __restrict__ xr,
                            const float* __restrict__ att,
                            float* __restrict__ ebuf, unsigned* __restrict__ emax) {
    int gw = (blockIdx.x * blockDim.x + threadIdx.x) >> 5;
    if (gw >= TE) return;
    int lane = threadIdx.x & 31;
    int s, d;
    if (gw < E) { s = ei[gw]; d = ei[E + gw]; }
    else        { s = gw - E; d = s; }
    const float* pl = xl + (size_t)s * (H * C);
    const float* pr = xr + (size_t)d * (H * C);
    float acc[H];
#pragma unroll
    for (int h = 0; h < H; ++h) acc[h] = 0.f;
#pragma unroll
    for (int h = 0; h < H; ++h) {
#pragma unroll
        for (int c0 = 0; c0 < C; c0 += 32) {
            int c = c0 + lane;
            float m = __ldg(pl + h * C + c) + __ldg(pr + h * C + c);
            m = (m > 0.f) ? m : 0.2f * m;
            acc[h] += m * __ldg(att + h * C + c);
        }
    }
#pragma unroll
    for (int off = 16; off; off >>= 1)
#pragma unroll
        for (int h = 0; h < H; ++h) acc[h] += __shfl_xor_sync(0xffffffffu, acc[h], off);
    if (lane == 0) {
#pragma unroll
        for (int h = 0; h < H; ++h) {
            ebuf[(size_t)gw * H + h] = acc[h];
            atomicMax(&emax[(size_t)d * H + h], fenc(acc[h]));
        }
    }
}

// ---------------- edge: exp(e - max) and segment sum ----------------
template <int H>
__global__ void edge_expsum(const int* __restrict__ ei, int E, int TE,
                            float* __restrict__ ebuf,
                            const unsigned* __restrict__ emax,
                            float* __restrict__ denom) {
    int idx = blockIdx.x * blockDim.x + threadIdx.x;
    if (idx >= TE * H) return;
    int e = idx / H, h = idx - e * H;
    int d = (e < E) ? ei[E + e] : (e - E);
    float mx = fdec(emax[(size_t)d * H + h]);
    float ex = __expf(ebuf[idx] - mx);
    ebuf[idx] = ex;
    atomicAdd(&denom[(size_t)d * H + h], ex);
}

// ---------------- edge: alpha * xl[src] scatter to dst ----------------
template <int H, int C>
__global__ void edge_aggregate(const int* __restrict__ ei, int E, int TE,
                               const float* __restrict__ xl,
                               const float* __restrict__ ebuf,
                               const float* __restrict__ denom,
                               float* __restrict__ agg) {
    int gw = (blockIdx.x * blockDim.x + threadIdx.x) >> 5;
    if (gw >= TE) return;
    int lane = threadIdx.x & 31;
    int s, d;
    if (gw < E) { s = ei[gw]; d = ei[E + gw]; }
    else        { s = gw - E; d = s; }
    const float* pl = xl + (size_t)s * (H * C);
    float* pa = agg + (size_t)d * (H * C);
#pragma unroll
    for (int h = 0; h < H; ++h) {
        float a = ebuf[(size_t)gw * H + h] / denom[(size_t)d * H + h];
#pragma unroll
        for (int c0 = 0; c0 < C; c0 += 32) {
            int c = c0 + lane;
            atomicAdd(pa + h * C + c, a * __ldg(pl + h * C + c));
        }
    }
}

// ---------------- node ops ----------------
__global__ void elu_bias(float* __restrict__ h, const float* __restrict__ bias, int n) {
    int idx = blockIdx.x * blockDim.x + threadIdx.x;
    if (idx >= n) return;
    float v = h[idx] + __ldg(bias + (idx & (HC1 - 1)));
    h[idx] = (v > 0.f) ? v : expm1f(v);
}

__global__ void out_bias(float* __restrict__ o, const float* __restrict__ bias, int n) {
    int idx = blockIdx.x * blockDim.x + threadIdx.x;
    if (idx >= n) return;
    o[idx] += __ldg(bias + (idx & (C2 - 1)));
}

// ---------------- host launch ----------------
static float*    p_xl1 = nullptr;
static float*    p_xr1 = nullptr;
static float*    p_agg = nullptr;
static float*    p_xl2 = nullptr;
static float*    p_xr2 = nullptr;
static float*    p_ebuf = nullptr;
static unsigned* p_emax = nullptr;
static float*    p_denom = nullptr;

extern "C" void kernel_launch(void* const* d_in, const int* in_sizes, int n_in,
                              void* d_out, int out_size) {
    if (!p_xl1) {
        void* p;
        cudaGetSymbolAddress(&p, g_xl1);   p_xl1  = (float*)p;
        cudaGetSymbolAddress(&p, g_xr1);   p_xr1  = (float*)p;
        cudaGetSymbolAddress(&p, g_agg);   p_agg  = (float*)p;
        cudaGetSymbolAddress(&p, g_xl2);   p_xl2  = (float*)p;
        cudaGetSymbolAddress(&p, g_xr2);   p_xr2  = (float*)p;
        cudaGetSymbolAddress(&p, g_ebuf);  p_ebuf = (float*)p;
        cudaGetSymbolAddress(&p, g_emax);  p_emax = (unsigned*)p;
        cudaGetSymbolAddress(&p, g_denom); p_denom = (float*)p;
    }

    const float* x    = (const float*)d_in[0];
    const int*   ei   = (const int*)d_in[1];
    const float* Wl1  = (const float*)d_in[2];
    const float* bl1  = (const float*)d_in[3];
    const float* Wr1  = (const float*)d_in[4];
    const float* br1  = (const float*)d_in[5];
    const float* att1 = (const float*)d_in[6];
    const float* bias1= (const float*)d_in[7];
    const float* Wl2  = (const float*)d_in[8];
    const float* bl2  = (const float*)d_in[9];
    const float* Wr2  = (const float*)d_in[10];
    const float* br2  = (const float*)d_in[11];
    const float* att2 = (const float*)d_in[12];
    const float* bias2= (const float*)d_in[13];
    float* out = (float*)d_out;

    const int IN = 128;
    const int N  = in_sizes[0] / IN;
    const int E  = in_sizes[1] / 2;
    const int TE = E + N;

    const int T = 256;
    auto cdiv = [](int a, int b) { return (a + b - 1) / b; };

    // ---- init layer1 scratch ----
    zerof<<<cdiv(N * HC1, T), T>>>(p_agg, N * HC1);
    zerof<<<cdiv(N * 4, T), T>>>((float*)p_emax, N * 4);  // encoded 0 == -inf sentinel
    zerof<<<cdiv(N * 4, T), T>>>(p_denom, N * 4);

    // ---- layer 1 GEMMs: xl1 = x@Wl1+bl1, xr1 = x@Wr1+br1 ----
    {
        dim3 grid(cdiv(HC1, 128), cdiv(N, 128));
        gemm_bias<<<grid, 256>>>(x, Wl1, bl1, p_xl1, N, IN, HC1);
        gemm_bias<<<grid, 256>>>(x, Wr1, br1, p_xr1, N, IN, HC1);
    }

    // ---- layer 1 edge phase (H=4, C=64) ----
    {
        int blocks = cdiv(TE * 32, T);
        edge_scores<4, 64><<<blocks, T>>>(ei, E, TE, p_xl1, p_xr1, att1, p_ebuf, p_emax);
        edge_expsum<4><<<cdiv(TE * 4, T), T>>>(ei, E, TE, p_ebuf, p_emax, p_denom);
        edge_aggregate<4, 64><<<blocks, T>>>(ei, E, TE, p_xl1, p_ebuf, p_denom, p_agg);
    }

    // ---- node: h = elu(agg + bias1) (in place) ----
    elu_bias<<<cdiv(N * HC1, T), T>>>(p_agg, bias1, N * HC1);

    // ---- init layer2 scratch + output ----
    zerof<<<cdiv(N, T), T>>>((float*)p_emax, N);
    zerof<<<cdiv(N, T), T>>>(p_denom, N);
    zerof<<<cdiv(N * C2, T), T>>>(out, N * C2);

    // ---- layer 2 GEMMs ----
    {
        dim3 grid(cdiv(C2, 128), cdiv(N, 128));
        gemm_bias<<<grid, 256>>>(p_agg, Wl2, bl2, p_xl2, N, HC1, C2);
        gemm_bias<<<grid, 256>>>(p_agg, Wr2, br2, p_xr2, N, HC1, C2);
    }

    // ---- layer 2 edge phase (H=1, C=64), aggregate straight into d_out ----
    {
        int blocks = cdiv(TE * 32, T);
        edge_scores<1, 64><<<blocks, T>>>(ei, E, TE, p_xl2, p_xr2, att2, p_ebuf, p_emax);
        edge_expsum<1><<<cdiv(TE, T), T>>>(ei, E, TE, p_ebuf, p_emax, p_denom);
        edge_aggregate<1, 64><<<blocks, T>>>(ei, E, TE, p_xl2, p_ebuf, p_denom, out);
    }

    // ---- final bias ----
    out_bias<<<cdiv(N * C2, T), T>>>(out, bias2, N * C2);
}

// round 3
// speedup vs baseline: 1.8871x; 1.8871x over previous
#include <cuda_runtime.h>
#include <cuda_bf16.h>
#include <cstddef>

// ---------------- problem constants (constexpr: no macro expansion hazards) ----
constexpr int kMaxN  = 50016;
constexpr int kMaxE  = 400000;
constexpr int kMaxTE = kMaxN + kMaxE;
constexpr int kHC1   = 256;   // H*HID layer1
constexpr int kC2    = 64;    // OUT layer2

// ---------------- device scratch ----------------
__device__ float g_xl1[(size_t)kMaxN * kHC1];
__device__ float g_xr1[(size_t)kMaxN * kHC1];
__device__ float g_h  [(size_t)kMaxN * kHC1];   // layer1 output (elu'd)
__device__ float g_xl2[(size_t)kMaxN * kC2];
__device__ float g_xr2[(size_t)kMaxN * kC2];
__device__ int   g_deg[kMaxN];
__device__ int   g_off[kMaxN + 1];
__device__ int   g_cur[kMaxN];
__device__ int   g_bsum[128];
__device__ int   g_csr_src[kMaxTE];

// ---------------- small utility kernels ----------------
__global__ void zeroi(int* p, int n) {
    int i = blockIdx.x * blockDim.x + threadIdx.x;
    if (i < n) p[i] = 0;
}

__global__ void count_deg(const int* __restrict__ ei, int E, int TE, int* __restrict__ deg) {
    int i = blockIdx.x * blockDim.x + threadIdx.x;
    if (i >= TE) return;
    int d = (i < E) ? ei[E + i] : (i - E);
    atomicAdd(&deg[d], 1);
}

// block-level exclusive scan (1024/block), writes block sums
__global__ void scan_block(const int* __restrict__ deg, int* __restrict__ off,
                           int* __restrict__ bsum, int n) {
    __shared__ int sh[1024];
    int tid = threadIdx.x;
    int i = blockIdx.x * 1024 + tid;
    int v = (i < n) ? deg[i] : 0;
    sh[tid] = v;
    __syncthreads();
    for (int o = 1; o < 1024; o <<= 1) {
        int t = (tid >= o) ? sh[tid - o] : 0;
        __syncthreads();
        sh[tid] += t;
        __syncthreads();
    }
    if (i < n) off[i] = sh[tid] - v;   // exclusive
    if (tid == 1023) bsum[blockIdx.x] = sh[1023];
}

__global__ void scan_sums(int* bsum, int nb) {
    if (threadIdx.x == 0) {
        int a = 0;
        for (int b = 0; b < nb; ++b) { int t = bsum[b]; bsum[b] = a; a += t; }
    }
}

__global__ void scan_add(int* __restrict__ off, const int* __restrict__ bsum,
                         int* __restrict__ cur, int n, int total) {
    int i = blockIdx.x * blockDim.x + threadIdx.x;
    if (i < n) {
        int v = off[i] + bsum[i >> 10];
        off[i] = v;
        cur[i] = v;
    }
    if (i == 0) off[n] = total;
}

__global__ void scatter_csr(const int* __restrict__ ei, int E, int TE,
                            int* __restrict__ cur, int* __restrict__ csr_src) {
    int i = blockIdx.x * blockDim.x + threadIdx.x;
    if (i >= TE) return;
    int s, d;
    if (i < E) { s = ei[i]; d = ei[E + i]; }
    else       { s = i - E; d = s; }
    int pos = atomicAdd(&cur[d], 1);
    csr_src[pos] = s;
}

// ---------------- dual-output SGEMM ----------------
// Cd1[M x n1] = A@B1 + bias1 ; Cd2[M x n2] = A@B2 + bias2, computed over
// concatenated column space (n1+n2 must be a multiple of 128, n1/n2 multiples of 64).
// 128x128 tile, BK=8, 256 threads, 8x8/thread with conflict-free {0,64} split.
__global__ __launch_bounds__(256, 2)
void gemm_dual(const float* __restrict__ A,
               const float* __restrict__ B1, const float* __restrict__ bias1,
               float* __restrict__ Cd1, int n1,
               const float* __restrict__ B2, const float* __restrict__ bias2,
               float* __restrict__ Cd2, int n2,
               int M, int K) {
    __shared__ float As[8][128];
    __shared__ float Bs[8][128];
    const int tid  = threadIdx.x;
    const int row0 = blockIdx.y * 128;
    const int col0 = blockIdx.x * 128;
    const int tx = tid & 15, ty = tid >> 4;

    float acc[8][8];
#pragma unroll
    for (int i = 0; i < 8; ++i)
#pragma unroll
        for (int j = 0; j < 8; ++j) acc[i][j] = 0.0f;

    const int arow  = tid >> 1;
    const int acol4 = (tid & 1) * 4;

    for (int k0 = 0; k0 < K; k0 += 8) {
        // A tile (128 x 8) transposed into As[k][m]
        if (row0 + arow < M) {
            float4 v = *(const float4*)(A + (size_t)(row0 + arow) * K + k0 + acol4);
            As[acol4 + 0][arow] = v.x;
            As[acol4 + 1][arow] = v.y;
            As[acol4 + 2][arow] = v.z;
            As[acol4 + 3][arow] = v.w;
        } else {
            As[acol4 + 0][arow] = 0.f; As[acol4 + 1][arow] = 0.f;
            As[acol4 + 2][arow] = 0.f; As[acol4 + 3][arow] = 0.f;
        }
        // B tile (8 x 128) with per-column source select
#pragma unroll
        for (int i = 0; i < 4; ++i) {
            int lin = tid + i * 256;
            int kk = lin >> 7, n = lin & 127;
            int cg = col0 + n;
            int kg = k0 + kk;
            float v;
            if (cg < n1) v = B1[(size_t)kg * n1 + cg];
            else         v = B2[(size_t)kg * n2 + (cg - n1)];
            Bs[kk][n] = v;
        }
        __syncthreads();
#pragma unroll
        for (int kk = 0; kk < 8; ++kk) {
            float4 a0 = *(const float4*)&As[kk][ty * 4];
            float4 a1 = *(const float4*)&As[kk][64 + ty * 4];
            float4 b0 = *(const float4*)&Bs[kk][tx * 4];
            float4 b1 = *(const float4*)&Bs[kk][64 + tx * 4];
            float a[8] = {a0.x, a0.y, a0.z, a0.w, a1.x, a1.y, a1.z, a1.w};
            float b[8] = {b0.x, b0.y, b0.z, b0.w, b1.x, b1.y, b1.z, b1.w};
#pragma unroll
            for (int i = 0; i < 8; ++i)
#pragma unroll
                for (int j = 0; j < 8; ++j) acc[i][j] += a[i] * b[j];
        }
        __syncthreads();
    }

#pragma unroll
    for (int i = 0; i < 8; ++i) {
        int r = row0 + ((i < 4) ? (ty * 4 + i) : (64 + ty * 4 + i - 4));
        if (r >= M) continue;
#pragma unroll
        for (int g = 0; g < 2; ++g) {
            int cg = col0 + g * 64 + tx * 4;
            const float* bias; float* Co; int Nc; int c;
            if (cg < n1) { bias = bias1; Co = Cd1; Nc = n1; c = cg; }
            else         { bias = bias2; Co = Cd2; Nc = n2; c = cg - n1; }
            float4 v;
            v.x = acc[i][g * 4 + 0] + __ldg(bias + c + 0);
            v.y = acc[i][g * 4 + 1] + __ldg(bias + c + 1);
            v.z = acc[i][g * 4 + 2] + __ldg(bias + c + 2);
            v.w = acc[i][g * 4 + 3] + __ldg(bias + c + 3);
            *(float4*)(Co + (size_t)r * Nc + c) = v;
        }
    }
}

// ---------------- fused GATv2 edge phase: one warp per dst node ----------------
// For each dst: keeps xr[dst], att in regs; loops CSR incoming edges doing
// gather xl[src] -> score -> online softmax -> weighted accumulate; then
// bias (+ optional elu) and a single streaming write.
template <int NH, int NC, int ELU>
__global__ void gat_fused(const int* __restrict__ off, const int* __restrict__ csr_src,
                          const float* __restrict__ xl, const float* __restrict__ xr,
                          const float* __restrict__ att, const float* __restrict__ bias,
                          float* __restrict__ out, int N) {
    constexpr int HC = NH * NC;
    constexpr int NR = HC / 32;
    int node = (blockIdx.x * blockDim.x + threadIdx.x) >> 5;
    if (node >= N) return;
    int lane = threadIdx.x & 31;

    float xr_d[NR], att_r[NR], acc[NR];
    float m[NH], s[NH];
    const float* prx = xr + (size_t)node * HC;
#pragma unroll
    for (int j = 0; j < NR; ++j) {
        int c = j * 32 + lane;
        xr_d[j] = __ldg(prx + c);
        att_r[j] = __ldg(att + c);
        acc[j] = 0.f;
    }
#pragma unroll
    for (int h = 0; h < NH; ++h) { m[h] = -1e30f; s[h] = 0.f; }

    int e0 = __ldg(off + node), e1 = __ldg(off + node + 1);
    for (int e = e0; e < e1; ++e) {
        int src = __ldg(csr_src + e);
        const float* pl = xl + (size_t)src * HC;
        float v[NR], q[NH];
#pragma unroll
        for (int h = 0; h < NH; ++h) q[h] = 0.f;
#pragma unroll
        for (int j = 0; j < NR; ++j) {
            v[j] = __ldg(pl + j * 32 + lane);
            float t = v[j] + xr_d[j];
            t = (t > 0.f) ? t : 0.2f * t;
            q[(j * 32) / NC] += t * att_r[j];
        }
#pragma unroll
        for (int o = 16; o; o >>= 1)
#pragma unroll
            for (int h = 0; h < NH; ++h) q[h] += __shfl_xor_sync(0xffffffffu, q[h], o);
#pragma unroll
        for (int h = 0; h < NH; ++h) {
            float eh = q[h];
            if (eh > m[h]) {
                float sc = __expf(m[h] - eh);
                s[h] *= sc;
#pragma unroll
                for (int j = 0; j < NR; ++j)
                    if ((j * 32) / NC == h) acc[j] *= sc;
                m[h] = eh;
            }
            float w = __expf(eh - m[h]);
            s[h] += w;
#pragma unroll
            for (int j = 0; j < NR; ++j)
                if ((j * 32) / NC == h) acc[j] += w * v[j];
        }
    }

    float* po = out + (size_t)node * HC;
#pragma unroll
    for (int j = 0; j < NR; ++j) {
        int c = j * 32 + lane;
        float o = acc[j] / s[(j * 32) / NC] + __ldg(bias + c);
        if (ELU) o = (o > 0.f) ? o : expm1f(o);
        po[c] = o;
    }
}

// ---------------- host launch ----------------
static float* p_xl1 = nullptr;
static float* p_xr1 = nullptr;
static float* p_h   = nullptr;
static float* p_xl2 = nullptr;
static float* p_xr2 = nullptr;
static int*   p_deg = nullptr;
static int*   p_off = nullptr;
static int*   p_cur = nullptr;
static int*   p_bsum = nullptr;
static int*   p_csr = nullptr;

extern "C" void kernel_launch(void* const* d_in, const int* in_sizes, int n_in,
                              void* d_out, int out_size) {
    if (!p_xl1) {
        void* p;
        cudaGetSymbolAddress(&p, g_xl1);     p_xl1 = (float*)p;
        cudaGetSymbolAddress(&p, g_xr1);     p_xr1 = (float*)p;
        cudaGetSymbolAddress(&p, g_h);       p_h   = (float*)p;
        cudaGetSymbolAddress(&p, g_xl2);     p_xl2 = (float*)p;
        cudaGetSymbolAddress(&p, g_xr2);     p_xr2 = (float*)p;
        cudaGetSymbolAddress(&p, g_deg);     p_deg = (int*)p;
        cudaGetSymbolAddress(&p, g_off);     p_off = (int*)p;
        cudaGetSymbolAddress(&p, g_cur);     p_cur = (int*)p;
        cudaGetSymbolAddress(&p, g_bsum);    p_bsum = (int*)p;
        cudaGetSymbolAddress(&p, g_csr_src); p_csr = (int*)p;
    }

    const float* x     = (const float*)d_in[0];
    const int*   ei    = (const int*)d_in[1];
    const float* Wl1   = (const float*)d_in[2];
    const float* bl1   = (const float*)d_in[3];
    const float* Wr1   = (const float*)d_in[4];
    const float* br1   = (const float*)d_in[5];
    const float* att1  = (const float*)d_in[6];
    const float* bias1 = (const float*)d_in[7];
    const float* Wl2   = (const float*)d_in[8];
    const float* bl2   = (const float*)d_in[9];
    const float* Wr2   = (const float*)d_in[10];
    const float* br2   = (const float*)d_in[11];
    const float* att2  = (const float*)d_in[12];
    const float* bias2 = (const float*)d_in[13];
    float* out = (float*)d_out;

    const int IN = 128;
    const int N  = in_sizes[0] / IN;
    const int E  = in_sizes[1] / 2;
    const int TE = E + N;

    const int T = 256;
    auto cdiv = [](int a, int b) { return (a + b - 1) / b; };

    // ---- CSR build (by dst), self loops appended ----
    zeroi<<<cdiv(N, T), T>>>(p_deg, N);
    count_deg<<<cdiv(TE, T), T>>>(ei, E, TE, p_deg);
    int nb = cdiv(N, 1024);
    scan_block<<<nb, 1024>>>(p_deg, p_off, p_bsum, N);
    scan_sums<<<1, 32>>>(p_bsum, nb);
    scan_add<<<cdiv(N, T), T>>>(p_off, p_bsum, p_cur, N, TE);
    scatter_csr<<<cdiv(TE, T), T>>>(ei, E, TE, p_cur, p_csr);

    // ---- layer 1: xl1|xr1 = x @ [Wl1|Wr1] + [bl1|br1] ----
    {
        dim3 grid((kHC1 + kHC1) / 128, cdiv(N, 128));
        gemm_dual<<<grid, 256>>>(x, Wl1, bl1, p_xl1, kHC1, Wr1, br1, p_xr1, kHC1, N, IN);
    }
    // ---- layer 1 fused edge phase -> h (bias1 + elu fused) ----
    gat_fused<4, 64, 1><<<cdiv(N * 32, T), T>>>(p_off, p_csr, p_xl1, p_xr1, att1, bias1, p_h, N);

    // ---- layer 2 GEMMs fused into one full 128-col tile ----
    {
        dim3 grid((kC2 + kC2) / 128, cdiv(N, 128));
        gemm_dual<<<grid, 256>>>(p_h, Wl2, bl2, p_xl2, kC2, Wr2, br2, p_xr2, kC2, N, kHC1);
    }
    // ---- layer 2 fused edge phase -> out (bias2 fused, no elu) ----
    gat_fused<1, 64, 0><<<cdiv(N * 32, T), T>>>(p_off, p_csr, p_xl2, p_xr2, att2, bias2, out, N);
}

// round 4
// speedup vs baseline: 2.9901x; 1.5844x over previous
#include <cuda_runtime.h>
#include <cuda_bf16.h>
#include <cstddef>

// ---------------- problem constants ----------------
constexpr int kMaxN  = 50016;
constexpr int kMaxE  = 400000;
constexpr int kMaxTE = kMaxN + kMaxE;
constexpr int kHC1   = 256;   // H*HID layer1
constexpr int kC2    = 64;    // OUT layer2

// ---------------- device scratch ----------------
__device__ float g_xl1[(size_t)kMaxN * kHC1];
__device__ float g_xr1[(size_t)kMaxN * kHC1];
__device__ float g_h  [(size_t)kMaxN * kHC1];
__device__ float g_xl2[(size_t)kMaxN * kC2];
__device__ float g_xr2[(size_t)kMaxN * kC2];
__device__ int   g_deg[kMaxN];
__device__ int   g_off[kMaxN + 1];
__device__ int   g_cur[kMaxN];
__device__ int   g_bsum[128];
__device__ int   g_csr_src[kMaxTE];

// ---------------- small utility kernels ----------------
__global__ void zeroi(int* p, int n) {
    int i = blockIdx.x * blockDim.x + threadIdx.x;
    if (i < n) p[i] = 0;
}

__global__ void count_deg(const int* __restrict__ ei, int E, int TE, int* __restrict__ deg) {
    int i = blockIdx.x * blockDim.x + threadIdx.x;
    if (i >= TE) return;
    int d = (i < E) ? ei[E + i] : (i - E);
    atomicAdd(&deg[d], 1);
}

__global__ void scan_block(const int* __restrict__ deg, int* __restrict__ off,
                           int* __restrict__ bsum, int n) {
    __shared__ int sh[1024];
    int tid = threadIdx.x;
    int i = blockIdx.x * 1024 + tid;
    int v = (i < n) ? deg[i] : 0;
    sh[tid] = v;
    __syncthreads();
    for (int o = 1; o < 1024; o <<= 1) {
        int t = (tid >= o) ? sh[tid - o] : 0;
        __syncthreads();
        sh[tid] += t;
        __syncthreads();
    }
    if (i < n) off[i] = sh[tid] - v;
    if (tid == 1023) bsum[blockIdx.x] = sh[1023];
}

__global__ void scan_sums(int* bsum, int nb) {
    if (threadIdx.x == 0) {
        int a = 0;
        for (int b = 0; b < nb; ++b) { int t = bsum[b]; bsum[b] = a; a += t; }
    }
}

__global__ void scan_add(int* __restrict__ off, const int* __restrict__ bsum,
                         int* __restrict__ cur, int n, int total) {
    int i = blockIdx.x * blockDim.x + threadIdx.x;
    if (i < n) {
        int v = off[i] + bsum[i >> 10];
        off[i] = v;
        cur[i] = v;
    }
    if (i == 0) off[n] = total;
}

__global__ void scatter_csr(const int* __restrict__ ei, int E, int TE,
                            int* __restrict__ cur, int* __restrict__ csr_src) {
    int i = blockIdx.x * blockDim.x + threadIdx.x;
    if (i >= TE) return;
    int s, d;
    if (i < E) { s = ei[i]; d = ei[E + i]; }
    else       { s = i - E; d = s; }
    int pos = atomicAdd(&cur[d], 1);
    csr_src[pos] = s;
}

// ---------------- TF32 tensor-core dual-output GEMM ----------------
// Cd1[M x n1] = A@B1 + bias1 ; Cd2[M x n2] = A@B2 + bias2 over concatenated
// column space. n1, n2 multiples of 64; n1+n2 multiple of 128; K multiple of 32.
// Block tile 128x128, BK=32, 8 warps in 4(M) x 2(N), warp tile 32x64.
// mma.sync.aligned.m16n8k8.row.col.f32.tf32.tf32.f32

__device__ __forceinline__ unsigned f2tf32(float f) {
    unsigned r;
    asm("cvt.rna.tf32.f32 %0, %1;" : "=r"(r) : "f"(f));
    return r;
}

__device__ __forceinline__ void mma_tf32(float* d, const unsigned* a, const unsigned* b) {
    asm volatile(
        "mma.sync.aligned.m16n8k8.row.col.f32.tf32.tf32.f32 "
        "{%0,%1,%2,%3}, {%4,%5,%6,%7}, {%8,%9}, {%0,%1,%2,%3};"
        : "+f"(d[0]), "+f"(d[1]), "+f"(d[2]), "+f"(d[3])
        : "r"(a[0]), "r"(a[1]), "r"(a[2]), "r"(a[3]), "r"(b[0]), "r"(b[1]));
}

constexpr int kAStr = 36;   // As row stride (floats): bank = lane, conflict-free
constexpr int kBStr = 136;  // Bs row stride (floats): bank = perm(lane), conflict-free

__global__ __launch_bounds__(256)
void gemm_dual_tc(const float* __restrict__ A,
                  const float* __restrict__ B1, const float* __restrict__ bias1,
                  float* __restrict__ Cd1, int n1,
                  const float* __restrict__ B2, const float* __restrict__ bias2,
                  float* __restrict__ Cd2, int n2,
                  int M, int K) {
    __shared__ float As[128 * kAStr];
    __shared__ float Bs[32 * kBStr];

    const int tid  = threadIdx.x;
    const int lane = tid & 31;
    const int wid  = tid >> 5;
    const int wm   = (wid & 3) * 32;   // warp M offset in tile
    const int wn   = (wid >> 2) * 64;  // warp N offset in tile
    const int row0 = blockIdx.y * 128;
    const int col0 = blockIdx.x * 128;

    float d[2][8][4];
#pragma unroll
    for (int mi = 0; mi < 2; ++mi)
#pragma unroll
        for (int ni = 0; ni < 8; ++ni)
#pragma unroll
            for (int r = 0; r < 4; ++r) d[mi][ni][r] = 0.f;

    // gmem->smem assignments
    const int a_row = tid >> 3;          // 0..31 (per pass of 32 rows)
    const int a_c4  = (tid & 7) * 4;     // float4 col
    const int b_row = tid >> 5;          // 0..7 (per pass of 8 rows)
    const int b_c4  = (tid & 31) * 4;

    for (int k0 = 0; k0 < K; k0 += 32) {
        // ---- load A tile (128 x 32), convert to tf32 bits at store ----
#pragma unroll
        for (int p = 0; p < 4; ++p) {
            int r = p * 32 + a_row;
            float4 v = make_float4(0.f, 0.f, 0.f, 0.f);
            if (row0 + r < M)
                v = *(const float4*)(A + (size_t)(row0 + r) * K + k0 + a_c4);
            float* dst = As + r * kAStr + a_c4;
            dst[0] = __uint_as_float(f2tf32(v.x));
            dst[1] = __uint_as_float(f2tf32(v.y));
            dst[2] = __uint_as_float(f2tf32(v.z));
            dst[3] = __uint_as_float(f2tf32(v.w));
        }
        // ---- load B tile (32 x 128) with column-source select ----
#pragma unroll
        for (int p = 0; p < 4; ++p) {
            int r = p * 8 + b_row;          // k within tile
            int kg = k0 + r;
            int cg = col0 + b_c4;
            float4 v;
            if (cg < n1) v = *(const float4*)(B1 + (size_t)kg * n1 + cg);
            else         v = *(const float4*)(B2 + (size_t)kg * n2 + (cg - n1));
            float* dst = Bs + r * kBStr + b_c4;
            dst[0] = __uint_as_float(f2tf32(v.x));
            dst[1] = __uint_as_float(f2tf32(v.y));
            dst[2] = __uint_as_float(f2tf32(v.z));
            dst[3] = __uint_as_float(f2tf32(v.w));
        }
        __syncthreads();

#pragma unroll
        for (int k8 = 0; k8 < 4; ++k8) {
            unsigned a[2][4], b[8][2];
            const int kk = k8 * 8 + (lane & 3);
            const int gr = lane >> 2;
#pragma unroll
            for (int mi = 0; mi < 2; ++mi) {
                int rbase = wm + mi * 16 + gr;
                a[mi][0] = __float_as_uint(As[rbase * kAStr + kk]);
                a[mi][1] = __float_as_uint(As[(rbase + 8) * kAStr + kk]);
                a[mi][2] = __float_as_uint(As[rbase * kAStr + kk + 4]);
                a[mi][3] = __float_as_uint(As[(rbase + 8) * kAStr + kk + 4]);
            }
#pragma unroll
            for (int ni = 0; ni < 8; ++ni) {
                int c = wn + ni * 8 + gr;
                b[ni][0] = __float_as_uint(Bs[kk * kBStr + c]);
                b[ni][1] = __float_as_uint(Bs[(kk + 4) * kBStr + c]);
            }
#pragma unroll
            for (int mi = 0; mi < 2; ++mi)
#pragma unroll
                for (int ni = 0; ni < 8; ++ni)
                    mma_tf32(d[mi][ni], a[mi], b[ni]);
        }
        __syncthreads();
    }

    // ---- epilogue: bias + store (each warp n-tile fully in one buffer) ----
    const float* bias = (col0 + wn < n1) ? bias1 : bias2;
    float* Co         = (col0 + wn < n1) ? Cd1 : Cd2;
    const int Nc      = (col0 + wn < n1) ? n1 : n2;
    const int cbase   = (col0 + wn < n1) ? (col0 + wn) : (col0 + wn - n1);

#pragma unroll
    for (int mi = 0; mi < 2; ++mi) {
#pragma unroll
        for (int half = 0; half < 2; ++half) {
            int r = row0 + wm + mi * 16 + (lane >> 2) + half * 8;
            if (r >= M) continue;
#pragma unroll
            for (int ni = 0; ni < 8; ++ni) {
                int c = cbase + ni * 8 + 2 * (lane & 3);
                float2 v;
                v.x = d[mi][ni][half * 2 + 0] + __ldg(bias + c + 0);
                v.y = d[mi][ni][half * 2 + 1] + __ldg(bias + c + 1);
                *(float2*)(Co + (size_t)r * Nc + c) = v;
            }
        }
    }
}

// ---------------- fused GATv2 edge phase: one warp per dst node ----------------
template <int NH, int NC, int ELU>
__global__ void gat_fused(const int* __restrict__ off, const int* __restrict__ csr_src,
                          const float* __restrict__ xl, const float* __restrict__ xr,
                          const float* __restrict__ att, const float* __restrict__ bias,
                          float* __restrict__ out, int N) {
    constexpr int HC = NH * NC;
    constexpr int NR = HC / 32;
    int node = (blockIdx.x * blockDim.x + threadIdx.x) >> 5;
    if (node >= N) return;
    int lane = threadIdx.x & 31;

    float xr_d[NR], att_r[NR], acc[NR];
    float m[NH], s[NH];
    const float* prx = xr + (size_t)node * HC;
#pragma unroll
    for (int j = 0; j < NR; ++j) {
        int c = j * 32 + lane;
        xr_d[j] = __ldg(prx + c);
        att_r[j] = __ldg(att + c);
        acc[j] = 0.f;
    }
#pragma unroll
    for (int h = 0; h < NH; ++h) { m[h] = -1e30f; s[h] = 0.f; }

    int e0 = __ldg(off + node), e1 = __ldg(off + node + 1);
    for (int e = e0; e < e1; ++e) {
        int src = __ldg(csr_src + e);
        const float* pl = xl + (size_t)src * HC;
        float v[NR], q[NH];
#pragma unroll
        for (int h = 0; h < NH; ++h) q[h] = 0.f;
#pragma unroll
        for (int j = 0; j < NR; ++j) {
            v[j] = __ldg(pl + j * 32 + lane);
            float t = v[j] + xr_d[j];
            t = (t > 0.f) ? t : 0.2f * t;
            q[(j * 32) / NC] += t * att_r[j];
        }
#pragma unroll
        for (int o = 16; o; o >>= 1)
#pragma unroll
            for (int h = 0; h < NH; ++h) q[h] += __shfl_xor_sync(0xffffffffu, q[h], o);
#pragma unroll
        for (int h = 0; h < NH; ++h) {
            float eh = q[h];
            if (eh > m[h]) {
                float sc = __expf(m[h] - eh);
                s[h] *= sc;
#pragma unroll
                for (int j = 0; j < NR; ++j)
                    if ((j * 32) / NC == h) acc[j] *= sc;
                m[h] = eh;
            }
            float w = __expf(eh - m[h]);
            s[h] += w;
#pragma unroll
            for (int j = 0; j < NR; ++j)
                if ((j * 32) / NC == h) acc[j] += w * v[j];
        }
    }

    float* po = out + (size_t)node * HC;
#pragma unroll
    for (int j = 0; j < NR; ++j) {
        int c = j * 32 + lane;
        float o = acc[j] / s[(j * 32) / NC] + __ldg(bias + c);
        if (ELU) o = (o > 0.f) ? o : expm1f(o);
        po[c] = o;
    }
}

// ---------------- host launch ----------------
static float* p_xl1 = nullptr;
static float* p_xr1 = nullptr;
static float* p_h   = nullptr;
static float* p_xl2 = nullptr;
static float* p_xr2 = nullptr;
static int*   p_deg = nullptr;
static int*   p_off = nullptr;
static int*   p_cur = nullptr;
static int*   p_bsum = nullptr;
static int*   p_csr = nullptr;

extern "C" void kernel_launch(void* const* d_in, const int* in_sizes, int n_in,
                              void* d_out, int out_size) {
    if (!p_xl1) {
        void* p;
        cudaGetSymbolAddress(&p, g_xl1);     p_xl1 = (float*)p;
        cudaGetSymbolAddress(&p, g_xr1);     p_xr1 = (float*)p;
        cudaGetSymbolAddress(&p, g_h);       p_h   = (float*)p;
        cudaGetSymbolAddress(&p, g_xl2);     p_xl2 = (float*)p;
        cudaGetSymbolAddress(&p, g_xr2);     p_xr2 = (float*)p;
        cudaGetSymbolAddress(&p, g_deg);     p_deg = (int*)p;
        cudaGetSymbolAddress(&p, g_off);     p_off = (int*)p;
        cudaGetSymbolAddress(&p, g_cur);     p_cur = (int*)p;
        cudaGetSymbolAddress(&p, g_bsum);    p_bsum = (int*)p;
        cudaGetSymbolAddress(&p, g_csr_src); p_csr = (int*)p;
    }

    const float* x     = (const float*)d_in[0];
    const int*   ei    = (const int*)d_in[1];
    const float* Wl1   = (const float*)d_in[2];
    const float* bl1   = (const float*)d_in[3];
    const float* Wr1   = (const float*)d_in[4];
    const float* br1   = (const float*)d_in[5];
    const float* att1  = (const float*)d_in[6];
    const float* bias1 = (const float*)d_in[7];
    const float* Wl2   = (const float*)d_in[8];
    const float* bl2   = (const float*)d_in[9];
    const float* Wr2   = (const float*)d_in[10];
    const float* br2   = (const float*)d_in[11];
    const float* att2  = (const float*)d_in[12];
    const float* bias2 = (const float*)d_in[13];
    float* out = (float*)d_out;

    const int IN = 128;
    const int N  = in_sizes[0] / IN;
    const int E  = in_sizes[1] / 2;
    const int TE = E + N;

    const int T = 256;
    auto cdiv = [](int a, int b) { return (a + b - 1) / b; };

    // ---- CSR build (by dst), self loops appended ----
    zeroi<<<cdiv(N, T), T>>>(p_deg, N);
    count_deg<<<cdiv(TE, T), T>>>(ei, E, TE, p_deg);
    int nb = cdiv(N, 1024);
    scan_block<<<nb, 1024>>>(p_deg, p_off, p_bsum, N);
    scan_sums<<<1, 32>>>(p_bsum, nb);
    scan_add<<<cdiv(N, T), T>>>(p_off, p_bsum, p_cur, N, TE);
    scatter_csr<<<cdiv(TE, T), T>>>(ei, E, TE, p_cur, p_csr);

    // ---- layer 1: xl1|xr1 = x @ [Wl1|Wr1] + [bl1|br1] (TF32 TC) ----
    {
        dim3 grid((kHC1 + kHC1) / 128, cdiv(N, 128));
        gemm_dual_tc<<<grid, 256>>>(x, Wl1, bl1, p_xl1, kHC1, Wr1, br1, p_xr1, kHC1, N, IN);
    }
    // ---- layer 1 fused edge phase -> h (bias1 + elu fused) ----
    gat_fused<4, 64, 1><<<cdiv(N * 32, T), T>>>(p_off, p_csr, p_xl1, p_xr1, att1, bias1, p_h, N);

    // ---- layer 2 GEMMs fused into one full 128-col tile (TF32 TC) ----
    {
        dim3 grid((kC2 + kC2) / 128, cdiv(N, 128));
        gemm_dual_tc<<<grid, 256>>>(p_h, Wl2, bl2, p_xl2, kC2, Wr2, br2, p_xr2, kC2, N, kHC1);
    }
    // ---- layer 2 fused edge phase -> out (bias2 fused, no elu) ----
    gat_fused<1, 64, 0><<<cdiv(N * 32, T), T>>>(p_off, p_csr, p_xl2, p_xr2, att2, bias2, out, N);
}

// round 5
// speedup vs baseline: 2.9974x; 1.0025x over previous
#include <cuda_runtime.h>
#include <cuda_bf16.h>
#include <cstddef>

// ---------------- problem constants ----------------
constexpr int kMaxN  = 50016;
constexpr int kMaxE  = 400000;
constexpr int kMaxTE = kMaxN + kMaxE;
constexpr int kHC1   = 256;   // H*HID layer1
constexpr int kC2    = 64;    // OUT layer2

// ---------------- device scratch ----------------
__device__ float g_xl1[(size_t)kMaxN * kHC1];
__device__ float g_xr1[(size_t)kMaxN * kHC1];
__device__ float g_h  [(size_t)kMaxN * kHC1];
__device__ float g_xl2[(size_t)kMaxN * kC2];
__device__ float g_xr2[(size_t)kMaxN * kC2];
__device__ int   g_deg[kMaxN];
__device__ int   g_off[kMaxN + 1];
__device__ int   g_cur[kMaxN];
__device__ int   g_bsum[128];
__device__ int   g_csr_src[kMaxTE];

// ---------------- small utility kernels ----------------
__global__ void zeroi(int* p, int n) {
    int i = blockIdx.x * blockDim.x + threadIdx.x;
    if (i < n) p[i] = 0;
}

__global__ void count_deg(const int* __restrict__ ei, int E, int TE, int* __restrict__ deg) {
    int i = blockIdx.x * blockDim.x + threadIdx.x;
    if (i >= TE) return;
    int d = (i < E) ? ei[E + i] : (i - E);
    atomicAdd(&deg[d], 1);
}

__global__ void scan_block(const int* __restrict__ deg, int* __restrict__ off,
                           int* __restrict__ bsum, int n) {
    __shared__ int sh[1024];
    int tid = threadIdx.x;
    int i = blockIdx.x * 1024 + tid;
    int v = (i < n) ? deg[i] : 0;
    sh[tid] = v;
    __syncthreads();
    for (int o = 1; o < 1024; o <<= 1) {
        int t = (tid >= o) ? sh[tid - o] : 0;
        __syncthreads();
        sh[tid] += t;
        __syncthreads();
    }
    if (i < n) off[i] = sh[tid] - v;
    if (tid == 1023) bsum[blockIdx.x] = sh[1023];
}

// parallel exclusive scan of <=128 block sums
__global__ void scan_sums(int* bsum, int nb) {
    __shared__ int sh[128];
    int t = threadIdx.x;
    int v = (t < nb) ? bsum[t] : 0;
    sh[t] = v;
    __syncthreads();
    for (int o = 1; o < 128; o <<= 1) {
        int u = (t >= o) ? sh[t - o] : 0;
        __syncthreads();
        sh[t] += u;
        __syncthreads();
    }
    if (t < nb) bsum[t] = sh[t] - v;   // exclusive
}

__global__ void scan_add(int* __restrict__ off, const int* __restrict__ bsum,
                         int* __restrict__ cur, int n, int total) {
    int i = blockIdx.x * blockDim.x + threadIdx.x;
    if (i < n) {
        int v = off[i] + bsum[i >> 10];
        off[i] = v;
        cur[i] = v;
    }
    if (i == 0) off[n] = total;
}

__global__ void scatter_csr(const int* __restrict__ ei, int E, int TE,
                            int* __restrict__ cur, int* __restrict__ csr_src) {
    int i = blockIdx.x * blockDim.x + threadIdx.x;
    if (i >= TE) return;
    int s, d;
    if (i < E) { s = ei[i]; d = ei[E + i]; }
    else       { s = i - E; d = s; }
    int pos = atomicAdd(&cur[d], 1);
    csr_src[pos] = s;
}

// ---------------- TF32 tensor-core dual-output GEMM ----------------
__device__ __forceinline__ unsigned f2tf32(float f) {
    unsigned r;
    asm("cvt.rna.tf32.f32 %0, %1;" : "=r"(r) : "f"(f));
    return r;
}

__device__ __forceinline__ void mma_tf32(float* d, const unsigned* a, const unsigned* b) {
    asm volatile(
        "mma.sync.aligned.m16n8k8.row.col.f32.tf32.tf32.f32 "
        "{%0,%1,%2,%3}, {%4,%5,%6,%7}, {%8,%9}, {%0,%1,%2,%3};"
        : "+f"(d[0]), "+f"(d[1]), "+f"(d[2]), "+f"(d[3])
        : "r"(a[0]), "r"(a[1]), "r"(a[2]), "r"(a[3]), "r"(b[0]), "r"(b[1]));
}

constexpr int kAStr = 36;   // As row stride (floats): conflict-free
constexpr int kBStr = 136;  // Bs row stride (floats): conflict-free

__global__ __launch_bounds__(256)
void gemm_dual_tc(const float* __restrict__ A,
                  const float* __restrict__ B1, const float* __restrict__ bias1,
                  float* __restrict__ Cd1, int n1,
                  const float* __restrict__ B2, const float* __restrict__ bias2,
                  float* __restrict__ Cd2, int n2,
                  int M, int K) {
    __shared__ float As[128 * kAStr];
    __shared__ float Bs[32 * kBStr];

    const int tid  = threadIdx.x;
    const int lane = tid & 31;
    const int wid  = tid >> 5;
    const int wm   = (wid & 3) * 32;
    const int wn   = (wid >> 2) * 64;
    const int row0 = blockIdx.y * 128;
    const int col0 = blockIdx.x * 128;

    float d[2][8][4];
#pragma unroll
    for (int mi = 0; mi < 2; ++mi)
#pragma unroll
        for (int ni = 0; ni < 8; ++ni)
#pragma unroll
            for (int r = 0; r < 4; ++r) d[mi][ni][r] = 0.f;

    const int a_row = tid >> 3;
    const int a_c4  = (tid & 7) * 4;
    const int b_row = tid >> 5;
    const int b_c4  = (tid & 31) * 4;

    for (int k0 = 0; k0 < K; k0 += 32) {
#pragma unroll
        for (int p = 0; p < 4; ++p) {
            int r = p * 32 + a_row;
            float4 v = make_float4(0.f, 0.f, 0.f, 0.f);
            if (row0 + r < M)
                v = *(const float4*)(A + (size_t)(row0 + r) * K + k0 + a_c4);
            float* dst = As + r * kAStr + a_c4;
            dst[0] = __uint_as_float(f2tf32(v.x));
            dst[1] = __uint_as_float(f2tf32(v.y));
            dst[2] = __uint_as_float(f2tf32(v.z));
            dst[3] = __uint_as_float(f2tf32(v.w));
        }
#pragma unroll
        for (int p = 0; p < 4; ++p) {
            int r = p * 8 + b_row;
            int kg = k0 + r;
            int cg = col0 + b_c4;
            float4 v;
            if (cg < n1) v = *(const float4*)(B1 + (size_t)kg * n1 + cg);
            else         v = *(const float4*)(B2 + (size_t)kg * n2 + (cg - n1));
            float* dst = Bs + r * kBStr + b_c4;
            dst[0] = __uint_as_float(f2tf32(v.x));
            dst[1] = __uint_as_float(f2tf32(v.y));
            dst[2] = __uint_as_float(f2tf32(v.z));
            dst[3] = __uint_as_float(f2tf32(v.w));
        }
        __syncthreads();

#pragma unroll
        for (int k8 = 0; k8 < 4; ++k8) {
            unsigned a[2][4], b[8][2];
            const int kk = k8 * 8 + (lane & 3);
            const int gr = lane >> 2;
#pragma unroll
            for (int mi = 0; mi < 2; ++mi) {
                int rbase = wm + mi * 16 + gr;
                a[mi][0] = __float_as_uint(As[rbase * kAStr + kk]);
                a[mi][1] = __float_as_uint(As[(rbase + 8) * kAStr + kk]);
                a[mi][2] = __float_as_uint(As[rbase * kAStr + kk + 4]);
                a[mi][3] = __float_as_uint(As[(rbase + 8) * kAStr + kk + 4]);
            }
#pragma unroll
            for (int ni = 0; ni < 8; ++ni) {
                int c = wn + ni * 8 + gr;
                b[ni][0] = __float_as_uint(Bs[kk * kBStr + c]);
                b[ni][1] = __float_as_uint(Bs[(kk + 4) * kBStr + c]);
            }
#pragma unroll
            for (int mi = 0; mi < 2; ++mi)
#pragma unroll
                for (int ni = 0; ni < 8; ++ni)
                    mma_tf32(d[mi][ni], a[mi], b[ni]);
        }
        __syncthreads();
    }

    const float* bias = (col0 + wn < n1) ? bias1 : bias2;
    float* Co         = (col0 + wn < n1) ? Cd1 : Cd2;
    const int Nc      = (col0 + wn < n1) ? n1 : n2;
    const int cbase   = (col0 + wn < n1) ? (col0 + wn) : (col0 + wn - n1);

#pragma unroll
    for (int mi = 0; mi < 2; ++mi) {
#pragma unroll
        for (int half = 0; half < 2; ++half) {
            int r = row0 + wm + mi * 16 + (lane >> 2) + half * 8;
            if (r >= M) continue;
#pragma unroll
            for (int ni = 0; ni < 8; ++ni) {
                int c = cbase + ni * 8 + 2 * (lane & 3);
                float2 v;
                v.x = d[mi][ni][half * 2 + 0] + __ldg(bias + c + 0);
                v.y = d[mi][ni][half * 2 + 1] + __ldg(bias + c + 1);
                *(float2*)(Co + (size_t)r * Nc + c) = v;
            }
        }
    }
}

// ---------------- fused GATv2 edge phase: one warp per dst node ----------------
template <int NH, int NC, int ELU>
__global__ void gat_fused(const int* __restrict__ off, const int* __restrict__ csr_src,
                          const float* __restrict__ xl, const float* __restrict__ xr,
                          const float* __restrict__ att, const float* __restrict__ bias,
                          float* __restrict__ out, int N) {
    constexpr int HC = NH * NC;
    constexpr int NR = HC / 32;
    int node = (blockIdx.x * blockDim.x + threadIdx.x) >> 5;
    if (node >= N) return;
    int lane = threadIdx.x & 31;

    float xr_d[NR], att_r[NR], acc[NR];
    float m[NH], s[NH];
    const float* prx = xr + (size_t)node * HC;
#pragma unroll
    for (int j = 0; j < NR; ++j) {
        int c = j * 32 + lane;
        xr_d[j] = __ldg(prx + c);
        att_r[j] = __ldg(att + c);
        acc[j] = 0.f;
    }
#pragma unroll
    for (int h = 0; h < NH; ++h) { m[h] = -1e30f; s[h] = 0.f; }

    int e0 = __ldg(off + node), e1 = __ldg(off + node + 1);
#pragma unroll 2
    for (int e = e0; e < e1; ++e) {
        int src = __ldg(csr_src + e);
        const float* pl = xl + (size_t)src * HC;
        float v[NR], q[NH];
#pragma unroll
        for (int h = 0; h < NH; ++h) q[h] = 0.f;
#pragma unroll
        for (int j = 0; j < NR; ++j) {
            v[j] = __ldg(pl + j * 32 + lane);
            float t = v[j] + xr_d[j];
            t = (t > 0.f) ? t : 0.2f * t;
            q[(j * 32) / NC] += t * att_r[j];
        }
#pragma unroll
        for (int o = 16; o; o >>= 1)
#pragma unroll
            for (int h = 0; h < NH; ++h) q[h] += __shfl_xor_sync(0xffffffffu, q[h], o);
#pragma unroll
        for (int h = 0; h < NH; ++h) {
            float eh = q[h];
            if (eh > m[h]) {
                float sc = __expf(m[h] - eh);
                s[h] *= sc;
#pragma unroll
                for (int j = 0; j < NR; ++j)
                    if ((j * 32) / NC == h) acc[j] *= sc;
                m[h] = eh;
            }
            float w = __expf(eh - m[h]);
            s[h] += w;
#pragma unroll
            for (int j = 0; j < NR; ++j)
                if ((j * 32) / NC == h) acc[j] += w * v[j];
        }
    }

    float* po = out + (size_t)node * HC;
#pragma unroll
    for (int j = 0; j < NR; ++j) {
        int c = j * 32 + lane;
        float o = acc[j] / s[(j * 32) / NC] + __ldg(bias + c);
        if (ELU) o = (o > 0.f) ? o : expm1f(o);
        po[c] = o;
    }
}

// ---------------- host launch ----------------
static float* p_xl1 = nullptr;
static float* p_xr1 = nullptr;
static float* p_h   = nullptr;
static float* p_xl2 = nullptr;
static float* p_xr2 = nullptr;
static int*   p_deg = nullptr;
static int*   p_off = nullptr;
static int*   p_cur = nullptr;
static int*   p_bsum = nullptr;
static int*   p_csr = nullptr;
static cudaStream_t s_side = nullptr;
static cudaEvent_t  s_fork = nullptr, s_join = nullptr;

extern "C" void kernel_launch(void* const* d_in, const int* in_sizes, int n_in,
                              void* d_out, int out_size) {
    if (!p_xl1) {
        void* p;
        cudaGetSymbolAddress(&p, g_xl1);     p_xl1 = (float*)p;
        cudaGetSymbolAddress(&p, g_xr1);     p_xr1 = (float*)p;
        cudaGetSymbolAddress(&p, g_h);       p_h   = (float*)p;
        cudaGetSymbolAddress(&p, g_xl2);     p_xl2 = (float*)p;
        cudaGetSymbolAddress(&p, g_xr2);     p_xr2 = (float*)p;
        cudaGetSymbolAddress(&p, g_deg);     p_deg = (int*)p;
        cudaGetSymbolAddress(&p, g_off);     p_off = (int*)p;
        cudaGetSymbolAddress(&p, g_cur);     p_cur = (int*)p;
        cudaGetSymbolAddress(&p, g_bsum);    p_bsum = (int*)p;
        cudaGetSymbolAddress(&p, g_csr_src); p_csr = (int*)p;
        cudaStreamCreateWithFlags(&s_side, cudaStreamNonBlocking);
        cudaEventCreateWithFlags(&s_fork, cudaEventDisableTiming);
        cudaEventCreateWithFlags(&s_join, cudaEventDisableTiming);
    }

    const float* x     = (const float*)d_in[0];
    const int*   ei    = (const int*)d_in[1];
    const float* Wl1   = (const float*)d_in[2];
    const float* bl1   = (const float*)d_in[3];
    const float* Wr1   = (const float*)d_in[4];
    const float* br1   = (const float*)d_in[5];
    const float* att1  = (const float*)d_in[6];
    const float* bias1 = (const float*)d_in[7];
    const float* Wl2   = (const float*)d_in[8];
    const float* bl2   = (const float*)d_in[9];
    const float* Wr2   = (const float*)d_in[10];
    const float* br2   = (const float*)d_in[11];
    const float* att2  = (const float*)d_in[12];
    const float* bias2 = (const float*)d_in[13];
    float* out = (float*)d_out;

    const int IN = 128;
    const int N  = in_sizes[0] / IN;
    const int E  = in_sizes[1] / 2;
    const int TE = E + N;

    const int T = 256;
    auto cdiv = [](int a, int b) { return (a + b - 1) / b; };

    // ---- fork: CSR build on side stream, concurrent with layer-1 GEMM ----
    cudaEventRecord(s_fork, 0);
    cudaStreamWaitEvent(s_side, s_fork, 0);

    zeroi<<<cdiv(N, T), T, 0, s_side>>>(p_deg, N);
    count_deg<<<cdiv(TE, T), T, 0, s_side>>>(ei, E, TE, p_deg);
    int nb = cdiv(N, 1024);
    scan_block<<<nb, 1024, 0, s_side>>>(p_deg, p_off, p_bsum, N);
    scan_sums<<<1, 128, 0, s_side>>>(p_bsum, nb);
    scan_add<<<cdiv(N, T), T, 0, s_side>>>(p_off, p_bsum, p_cur, N, TE);
    scatter_csr<<<cdiv(TE, T), T, 0, s_side>>>(ei, E, TE, p_cur, p_csr);
    cudaEventRecord(s_join, s_side);

    // ---- layer 1 GEMM on main stream (overlapped with CSR build) ----
    {
        dim3 grid((kHC1 + kHC1) / 128, cdiv(N, 128));
        gemm_dual_tc<<<grid, 256>>>(x, Wl1, bl1, p_xl1, kHC1, Wr1, br1, p_xr1, kHC1, N, IN);
    }

    // ---- join, then fused edge phase layer 1 ----
    cudaStreamWaitEvent(0, s_join, 0);
    gat_fused<4, 64, 1><<<cdiv(N * 32, T), T>>>(p_off, p_csr, p_xl1, p_xr1, att1, bias1, p_h, N);

    // ---- layer 2 GEMM ----
    {
        dim3 grid((kC2 + kC2) / 128, cdiv(N, 128));
        gemm_dual_tc<<<grid, 256>>>(p_h, Wl2, bl2, p_xl2, kC2, Wr2, br2, p_xr2, kC2, N, kHC1);
    }
    // ---- layer 2 fused edge phase -> out ----
    gat_fused<1, 64, 0><<<cdiv(N * 32, T), T>>>(p_off, p_csr, p_xl2, p_xr2, att2, bias2, out, N);
}

// round 6
// speedup vs baseline: 3.4910x; 1.1647x over previous
#include <cuda_runtime.h>
#include <cuda_bf16.h>
#include <cstddef>

// ---------------- problem constants ----------------
constexpr int kMaxN  = 50016;
constexpr int kMaxE  = 400000;
constexpr int kMaxTE = kMaxN + kMaxE;
constexpr int kHC1   = 256;   // H*HID layer1
constexpr int kC2    = 64;    // OUT layer2

// ---------------- device scratch ----------------
__device__ float g_xl1[(size_t)kMaxN * kHC1];
__device__ float g_xr1[(size_t)kMaxN * kHC1];
__device__ float g_h  [(size_t)kMaxN * kHC1];
__device__ float g_xl2[(size_t)kMaxN * kC2];
__device__ float g_xr2[(size_t)kMaxN * kC2];
__device__ int   g_deg[kMaxN];
__device__ int   g_off[kMaxN + 1];
__device__ int   g_cur[kMaxN];
__device__ int   g_bsum[128];
__device__ int   g_csr_src[kMaxTE];

// ---------------- small utility kernels ----------------
__global__ void zeroi(int* p, int n) {
    int i = blockIdx.x * blockDim.x + threadIdx.x;
    if (i < n) p[i] = 0;
}

__global__ void count_deg(const int* __restrict__ ei, int E, int TE, int* __restrict__ deg) {
    int i = blockIdx.x * blockDim.x + threadIdx.x;
    if (i >= TE) return;
    int d = (i < E) ? ei[E + i] : (i - E);
    atomicAdd(&deg[d], 1);
}

__global__ void scan_block(const int* __restrict__ deg, int* __restrict__ off,
                           int* __restrict__ bsum, int n) {
    __shared__ int sh[1024];
    int tid = threadIdx.x;
    int i = blockIdx.x * 1024 + tid;
    int v = (i < n) ? deg[i] : 0;
    sh[tid] = v;
    __syncthreads();
    for (int o = 1; o < 1024; o <<= 1) {
        int t = (tid >= o) ? sh[tid - o] : 0;
        __syncthreads();
        sh[tid] += t;
        __syncthreads();
    }
    if (i < n) off[i] = sh[tid] - v;
    if (tid == 1023) bsum[blockIdx.x] = sh[1023];
}

__global__ void scan_sums(int* bsum, int nb) {
    __shared__ int sh[128];
    int t = threadIdx.x;
    int v = (t < nb) ? bsum[t] : 0;
    sh[t] = v;
    __syncthreads();
    for (int o = 1; o < 128; o <<= 1) {
        int u = (t >= o) ? sh[t - o] : 0;
        __syncthreads();
        sh[t] += u;
        __syncthreads();
    }
    if (t < nb) bsum[t] = sh[t] - v;
}

__global__ void scan_add(int* __restrict__ off, const int* __restrict__ bsum,
                         int* __restrict__ cur, int n, int total) {
    int i = blockIdx.x * blockDim.x + threadIdx.x;
    if (i < n) {
        int v = off[i] + bsum[i >> 10];
        off[i] = v;
        cur[i] = v;
    }
    if (i == 0) off[n] = total;
}

__global__ void scatter_csr(const int* __restrict__ ei, int E, int TE,
                            int* __restrict__ cur, int* __restrict__ csr_src) {
    int i = blockIdx.x * blockDim.x + threadIdx.x;
    if (i >= TE) return;
    int s, d;
    if (i < E) { s = ei[i]; d = ei[E + i]; }
    else       { s = i - E; d = s; }
    int pos = atomicAdd(&cur[d], 1);
    csr_src[pos] = s;
}

// ---------------- TF32 tensor-core dual-output GEMM ----------------
__device__ __forceinline__ unsigned f2tf32(float f) {
    unsigned r;
    asm("cvt.rna.tf32.f32 %0, %1;" : "=r"(r) : "f"(f));
    return r;
}

__device__ __forceinline__ void mma_tf32(float* d, const unsigned* a, const unsigned* b) {
    asm volatile(
        "mma.sync.aligned.m16n8k8.row.col.f32.tf32.tf32.f32 "
        "{%0,%1,%2,%3}, {%4,%5,%6,%7}, {%8,%9}, {%0,%1,%2,%3};"
        : "+f"(d[0]), "+f"(d[1]), "+f"(d[2]), "+f"(d[3])
        : "r"(a[0]), "r"(a[1]), "r"(a[2]), "r"(a[3]), "r"(b[0]), "r"(b[1]));
}

constexpr int kAStr = 36;
constexpr int kBStr = 136;

__global__ __launch_bounds__(256)
void gemm_dual_tc(const float* __restrict__ A,
                  const float* __restrict__ B1, const float* __restrict__ bias1,
                  float* __restrict__ Cd1, int n1,
                  const float* __restrict__ B2, const float* __restrict__ bias2,
                  float* __restrict__ Cd2, int n2,
                  int M, int K) {
    __shared__ float As[128 * kAStr];
    __shared__ float Bs[32 * kBStr];

    const int tid  = threadIdx.x;
    const int lane = tid & 31;
    const int wid  = tid >> 5;
    const int wm   = (wid & 3) * 32;
    const int wn   = (wid >> 2) * 64;
    const int row0 = blockIdx.y * 128;
    const int col0 = blockIdx.x * 128;

    float d[2][8][4];
#pragma unroll
    for (int mi = 0; mi < 2; ++mi)
#pragma unroll
        for (int ni = 0; ni < 8; ++ni)
#pragma unroll
            for (int r = 0; r < 4; ++r) d[mi][ni][r] = 0.f;

    const int a_row = tid >> 3;
    const int a_c4  = (tid & 7) * 4;
    const int b_row = tid >> 5;
    const int b_c4  = (tid & 31) * 4;

    for (int k0 = 0; k0 < K; k0 += 32) {
#pragma unroll
        for (int p = 0; p < 4; ++p) {
            int r = p * 32 + a_row;
            float4 v = make_float4(0.f, 0.f, 0.f, 0.f);
            if (row0 + r < M)
                v = *(const float4*)(A + (size_t)(row0 + r) * K + k0 + a_c4);
            float* dst = As + r * kAStr + a_c4;
            dst[0] = __uint_as_float(f2tf32(v.x));
            dst[1] = __uint_as_float(f2tf32(v.y));
            dst[2] = __uint_as_float(f2tf32(v.z));
            dst[3] = __uint_as_float(f2tf32(v.w));
        }
#pragma unroll
        for (int p = 0; p < 4; ++p) {
            int r = p * 8 + b_row;
            int kg = k0 + r;
            int cg = col0 + b_c4;
            float4 v;
            if (cg < n1) v = *(const float4*)(B1 + (size_t)kg * n1 + cg);
            else         v = *(const float4*)(B2 + (size_t)kg * n2 + (cg - n1));
            float* dst = Bs + r * kBStr + b_c4;
            dst[0] = __uint_as_float(f2tf32(v.x));
            dst[1] = __uint_as_float(f2tf32(v.y));
            dst[2] = __uint_as_float(f2tf32(v.z));
            dst[3] = __uint_as_float(f2tf32(v.w));
        }
        __syncthreads();

#pragma unroll
        for (int k8 = 0; k8 < 4; ++k8) {
            unsigned a[2][4], b[8][2];
            const int kk = k8 * 8 + (lane & 3);
            const int gr = lane >> 2;
#pragma unroll
            for (int mi = 0; mi < 2; ++mi) {
                int rbase = wm + mi * 16 + gr;
                a[mi][0] = __float_as_uint(As[rbase * kAStr + kk]);
                a[mi][1] = __float_as_uint(As[(rbase + 8) * kAStr + kk]);
                a[mi][2] = __float_as_uint(As[rbase * kAStr + kk + 4]);
                a[mi][3] = __float_as_uint(As[(rbase + 8) * kAStr + kk + 4]);
            }
#pragma unroll
            for (int ni = 0; ni < 8; ++ni) {
                int c = wn + ni * 8 + gr;
                b[ni][0] = __float_as_uint(Bs[kk * kBStr + c]);
                b[ni][1] = __float_as_uint(Bs[(kk + 4) * kBStr + c]);
            }
#pragma unroll
            for (int mi = 0; mi < 2; ++mi)
#pragma unroll
                for (int ni = 0; ni < 8; ++ni)
                    mma_tf32(d[mi][ni], a[mi], b[ni]);
        }
        __syncthreads();
    }

    const float* bias = (col0 + wn < n1) ? bias1 : bias2;
    float* Co         = (col0 + wn < n1) ? Cd1 : Cd2;
    const int Nc      = (col0 + wn < n1) ? n1 : n2;
    const int cbase   = (col0 + wn < n1) ? (col0 + wn) : (col0 + wn - n1);

#pragma unroll
    for (int mi = 0; mi < 2; ++mi) {
#pragma unroll
        for (int half = 0; half < 2; ++half) {
            int r = row0 + wm + mi * 16 + (lane >> 2) + half * 8;
            if (r >= M) continue;
#pragma unroll
            for (int ni = 0; ni < 8; ++ni) {
                int c = cbase + ni * 8 + 2 * (lane & 3);
                float2 v;
                v.x = d[mi][ni][half * 2 + 0] + __ldg(bias + c + 0);
                v.y = d[mi][ni][half * 2 + 1] + __ldg(bias + c + 1);
                *(float2*)(Co + (size_t)r * Nc + c) = v;
            }
        }
    }
}

// ---------------- helpers ----------------
__device__ __forceinline__ float leaky(float t) { return fmaxf(t, 0.2f * t); }

// ---------------- layer-1 fused edge phase (H=4, C=64, +bias +elu) ----------------
// One warp per dst node. float4 lanes: vec0 covers cols lane*4 (heads 0/1 by lane
// half), vec1 covers cols 128+lane*4 (heads 2/3). Each lane half keeps softmax
// state only for its own two heads; butterfly stays within the 16-lane half.
__global__ void gat_fused_l1(const int* __restrict__ off, const int* __restrict__ csr,
                             const float* __restrict__ xl, const float* __restrict__ xr,
                             const float* __restrict__ att, const float* __restrict__ bias,
                             float* __restrict__ out, int N) {
    int node = (blockIdx.x * blockDim.x + threadIdx.x) >> 5;
    if (node >= N) return;
    int lane = threadIdx.x & 31;

    const float4* prx = (const float4*)(xr + (size_t)node * 256);
    float4 xr0 = __ldg(prx + lane);
    float4 xr1 = __ldg(prx + 32 + lane);
    const float4* pat = (const float4*)att;
    float4 at0 = __ldg(pat + lane);
    float4 at1 = __ldg(pat + 32 + lane);

    float4 acc0 = make_float4(0.f, 0.f, 0.f, 0.f);
    float4 acc1 = make_float4(0.f, 0.f, 0.f, 0.f);
    float m0 = -1e30f, s0 = 0.f;   // own head for vec0 (head 0 or 1)
    float m1 = -1e30f, s1 = 0.f;   // own head for vec1 (head 2 or 3)

    int e0 = __ldg(off + node), e1 = __ldg(off + node + 1);
#pragma unroll 2
    for (int e = e0; e < e1; ++e) {
        int src = __ldg(csr + e);
        const float4* pl = (const float4*)(xl + (size_t)src * 256);
        float4 v0 = __ldg(pl + lane);
        float4 v1 = __ldg(pl + 32 + lane);

        float q0 = leaky(v0.x + xr0.x) * at0.x;
        q0 = fmaf(leaky(v0.y + xr0.y), at0.y, q0);
        q0 = fmaf(leaky(v0.z + xr0.z), at0.z, q0);
        q0 = fmaf(leaky(v0.w + xr0.w), at0.w, q0);
        float q1 = leaky(v1.x + xr1.x) * at1.x;
        q1 = fmaf(leaky(v1.y + xr1.y), at1.y, q1);
        q1 = fmaf(leaky(v1.z + xr1.z), at1.z, q1);
        q1 = fmaf(leaky(v1.w + xr1.w), at1.w, q1);

#pragma unroll
        for (int o = 8; o; o >>= 1) {
            q0 += __shfl_xor_sync(0xffffffffu, q0, o);
            q1 += __shfl_xor_sync(0xffffffffu, q1, o);
        }

        // branchless online softmax, own head only
        {
            float nm = fmaxf(m0, q0);
            float sc = __expf(m0 - nm);
            float w  = __expf(q0 - nm);
            s0 = s0 * sc + w;
            m0 = nm;
            acc0.x = fmaf(acc0.x, sc, w * v0.x);
            acc0.y = fmaf(acc0.y, sc, w * v0.y);
            acc0.z = fmaf(acc0.z, sc, w * v0.z);
            acc0.w = fmaf(acc0.w, sc, w * v0.w);
        }
        {
            float nm = fmaxf(m1, q1);
            float sc = __expf(m1 - nm);
            float w  = __expf(q1 - nm);
            s1 = s1 * sc + w;
            m1 = nm;
            acc1.x = fmaf(acc1.x, sc, w * v1.x);
            acc1.y = fmaf(acc1.y, sc, w * v1.y);
            acc1.z = fmaf(acc1.z, sc, w * v1.z);
            acc1.w = fmaf(acc1.w, sc, w * v1.w);
        }
    }

    float inv0 = 1.f / s0, inv1 = 1.f / s1;
    const float4* pb = (const float4*)bias;
    float4 b0 = __ldg(pb + lane), b1 = __ldg(pb + 32 + lane);
    float4 o0, o1;
    o0.x = acc0.x * inv0 + b0.x;  o0.y = acc0.y * inv0 + b0.y;
    o0.z = acc0.z * inv0 + b0.z;  o0.w = acc0.w * inv0 + b0.w;
    o1.x = acc1.x * inv1 + b1.x;  o1.y = acc1.y * inv1 + b1.y;
    o1.z = acc1.z * inv1 + b1.z;  o1.w = acc1.w * inv1 + b1.w;
    // elu
    o0.x = (o0.x > 0.f) ? o0.x : expm1f(o0.x);
    o0.y = (o0.y > 0.f) ? o0.y : expm1f(o0.y);
    o0.z = (o0.z > 0.f) ? o0.z : expm1f(o0.z);
    o0.w = (o0.w > 0.f) ? o0.w : expm1f(o0.w);
    o1.x = (o1.x > 0.f) ? o1.x : expm1f(o1.x);
    o1.y = (o1.y > 0.f) ? o1.y : expm1f(o1.y);
    o1.z = (o1.z > 0.f) ? o1.z : expm1f(o1.z);
    o1.w = (o1.w > 0.f) ? o1.w : expm1f(o1.w);

    float4* po = (float4*)(out + (size_t)node * 256);
    po[lane] = o0;
    po[32 + lane] = o1;
}

// ---------------- layer-2 fused edge phase (H=1, C=64, +bias) ----------------
__global__ void gat_fused_l2(const int* __restrict__ off, const int* __restrict__ csr,
                             const float* __restrict__ xl, const float* __restrict__ xr,
                             const float* __restrict__ att, const float* __restrict__ bias,
                             float* __restrict__ out, int N) {
    int node = (blockIdx.x * blockDim.x + threadIdx.x) >> 5;
    if (node >= N) return;
    int lane = threadIdx.x & 31;

    const float2* prx = (const float2*)(xr + (size_t)node * 64);
    float2 xrv = __ldg(prx + lane);
    float2 atv = __ldg((const float2*)att + lane);

    float2 acc = make_float2(0.f, 0.f);
    float m = -1e30f, s = 0.f;

    int e0 = __ldg(off + node), e1 = __ldg(off + node + 1);
#pragma unroll 2
    for (int e = e0; e < e1; ++e) {
        int src = __ldg(csr + e);
        float2 v = __ldg((const float2*)(xl + (size_t)src * 64) + lane);
        float q = leaky(v.x + xrv.x) * atv.x;
        q = fmaf(leaky(v.y + xrv.y), atv.y, q);
#pragma unroll
        for (int o = 16; o; o >>= 1) q += __shfl_xor_sync(0xffffffffu, q, o);
        float nm = fmaxf(m, q);
        float sc = __expf(m - nm);
        float w  = __expf(q - nm);
        s = s * sc + w;
        m = nm;
        acc.x = fmaf(acc.x, sc, w * v.x);
        acc.y = fmaf(acc.y, sc, w * v.y);
    }

    float inv = 1.f / s;
    float2 bv = __ldg((const float2*)bias + lane);
    float2 o;
    o.x = acc.x * inv + bv.x;
    o.y = acc.y * inv + bv.y;
    *((float2*)(out + (size_t)node * 64) + lane) = o;
}

// ---------------- host launch ----------------
static float* p_xl1 = nullptr;
static float* p_xr1 = nullptr;
static float* p_h   = nullptr;
static float* p_xl2 = nullptr;
static float* p_xr2 = nullptr;
static int*   p_deg = nullptr;
static int*   p_off = nullptr;
static int*   p_cur = nullptr;
static int*   p_bsum = nullptr;
static int*   p_csr = nullptr;
static cudaStream_t s_side = nullptr;
static cudaEvent_t  s_fork = nullptr, s_join = nullptr;

extern "C" void kernel_launch(void* const* d_in, const int* in_sizes, int n_in,
                              void* d_out, int out_size) {
    if (!p_xl1) {
        void* p;
        cudaGetSymbolAddress(&p, g_xl1);     p_xl1 = (float*)p;
        cudaGetSymbolAddress(&p, g_xr1);     p_xr1 = (float*)p;
        cudaGetSymbolAddress(&p, g_h);       p_h   = (float*)p;
        cudaGetSymbolAddress(&p, g_xl2);     p_xl2 = (float*)p;
        cudaGetSymbolAddress(&p, g_xr2);     p_xr2 = (float*)p;
        cudaGetSymbolAddress(&p, g_deg);     p_deg = (int*)p;
        cudaGetSymbolAddress(&p, g_off);     p_off = (int*)p;
        cudaGetSymbolAddress(&p, g_cur);     p_cur = (int*)p;
        cudaGetSymbolAddress(&p, g_bsum);    p_bsum = (int*)p;
        cudaGetSymbolAddress(&p, g_csr_src); p_csr = (int*)p;
        cudaStreamCreateWithFlags(&s_side, cudaStreamNonBlocking);
        cudaEventCreateWithFlags(&s_fork, cudaEventDisableTiming);
        cudaEventCreateWithFlags(&s_join, cudaEventDisableTiming);
    }

    const float* x     = (const float*)d_in[0];
    const int*   ei    = (const int*)d_in[1];
    const float* Wl1   = (const float*)d_in[2];
    const float* bl1   = (const float*)d_in[3];
    const float* Wr1   = (const float*)d_in[4];
    const float* br1   = (const float*)d_in[5];
    const float* att1  = (const float*)d_in[6];
    const float* bias1 = (const float*)d_in[7];
    const float* Wl2   = (const float*)d_in[8];
    const float* bl2   = (const float*)d_in[9];
    const float* Wr2   = (const float*)d_in[10];
    const float* br2   = (const float*)d_in[11];
    const float* att2  = (const float*)d_in[12];
    const float* bias2 = (const float*)d_in[13];
    float* out = (float*)d_out;

    const int IN = 128;
    const int N  = in_sizes[0] / IN;
    const int E  = in_sizes[1] / 2;
    const int TE = E + N;

    const int T = 256;
    auto cdiv = [](int a, int b) { return (a + b - 1) / b; };

    // ---- fork: CSR build on side stream, concurrent with layer-1 GEMM ----
    cudaEventRecord(s_fork, 0);
    cudaStreamWaitEvent(s_side, s_fork, 0);

    zeroi<<<cdiv(N, T), T, 0, s_side>>>(p_deg, N);
    count_deg<<<cdiv(TE, T), T, 0, s_side>>>(ei, E, TE, p_deg);
    int nb = cdiv(N, 1024);
    scan_block<<<nb, 1024, 0, s_side>>>(p_deg, p_off, p_bsum, N);
    scan_sums<<<1, 128, 0, s_side>>>(p_bsum, nb);
    scan_add<<<cdiv(N, T), T, 0, s_side>>>(p_off, p_bsum, p_cur, N, TE);
    scatter_csr<<<cdiv(TE, T), T, 0, s_side>>>(ei, E, TE, p_cur, p_csr);
    cudaEventRecord(s_join, s_side);

    // ---- layer 1 GEMM on main stream ----
    {
        dim3 grid((kHC1 + kHC1) / 128, cdiv(N, 128));
        gemm_dual_tc<<<grid, 256>>>(x, Wl1, bl1, p_xl1, kHC1, Wr1, br1, p_xr1, kHC1, N, IN);
    }

    // ---- join, then fused edge phase layer 1 ----
    cudaStreamWaitEvent(0, s_join, 0);
    gat_fused_l1<<<cdiv(N * 32, T), T>>>(p_off, p_csr, p_xl1, p_xr1, att1, bias1, p_h, N);

    // ---- layer 2 GEMM ----
    {
        dim3 grid((kC2 + kC2) / 128, cdiv(N, 128));
        gemm_dual_tc<<<grid, 256>>>(p_h, Wl2, bl2, p_xl2, kC2, Wr2, br2, p_xr2, kC2, N, kHC1);
    }
    // ---- layer 2 fused edge phase -> out ----
    gat_fused_l2<<<cdiv(N * 32, T), T>>>(p_off, p_csr, p_xl2, p_xr2, att2, bias2, out, N);
}

// round 7
// speedup vs baseline: 3.6372x; 1.0419x over previous
#include <cuda_runtime.h>
#include <cuda_fp16.h>
#include <cstddef>

// ---------------- problem constants ----------------
constexpr int kMaxN  = 50016;
constexpr int kMaxE  = 400000;
constexpr int kMaxTE = kMaxN + kMaxE;
constexpr int kHC1   = 256;   // H*HID layer1
constexpr int kC2    = 64;    // OUT layer2

// ---------------- device scratch ----------------
__device__ __half g_xl1[(size_t)kMaxN * kHC1];  // gathered operand: fp16
__device__ float  g_xr1[(size_t)kMaxN * kHC1];
__device__ float  g_h  [(size_t)kMaxN * kHC1];
__device__ __half g_xl2[(size_t)kMaxN * kC2];   // gathered operand: fp16
__device__ float  g_xr2[(size_t)kMaxN * kC2];
__device__ int    g_deg[kMaxN];
__device__ int    g_off[kMaxN + 1];
__device__ int    g_cur[kMaxN];
__device__ int    g_bsum[128];
__device__ int    g_csr_src[kMaxTE];

// ---------------- small utility kernels ----------------
__global__ void zeroi(int* p, int n) {
    int i = blockIdx.x * blockDim.x + threadIdx.x;
    if (i < n) p[i] = 0;
}

__global__ void count_deg(const int* __restrict__ ei, int E, int TE, int* __restrict__ deg) {
    int i = blockIdx.x * blockDim.x + threadIdx.x;
    if (i >= TE) return;
    int d = (i < E) ? ei[E + i] : (i - E);
    atomicAdd(&deg[d], 1);
}

__global__ void scan_block(const int* __restrict__ deg, int* __restrict__ off,
                           int* __restrict__ bsum, int n) {
    __shared__ int sh[1024];
    int tid = threadIdx.x;
    int i = blockIdx.x * 1024 + tid;
    int v = (i < n) ? deg[i] : 0;
    sh[tid] = v;
    __syncthreads();
    for (int o = 1; o < 1024; o <<= 1) {
        int t = (tid >= o) ? sh[tid - o] : 0;
        __syncthreads();
        sh[tid] += t;
        __syncthreads();
    }
    if (i < n) off[i] = sh[tid] - v;
    if (tid == 1023) bsum[blockIdx.x] = sh[1023];
}

__global__ void scan_sums(int* bsum, int nb) {
    __shared__ int sh[128];
    int t = threadIdx.x;
    int v = (t < nb) ? bsum[t] : 0;
    sh[t] = v;
    __syncthreads();
    for (int o = 1; o < 128; o <<= 1) {
        int u = (t >= o) ? sh[t - o] : 0;
        __syncthreads();
        sh[t] += u;
        __syncthreads();
    }
    if (t < nb) bsum[t] = sh[t] - v;
}

__global__ void scan_add(int* __restrict__ off, const int* __restrict__ bsum,
                         int* __restrict__ cur, int n, int total) {
    int i = blockIdx.x * blockDim.x + threadIdx.x;
    if (i < n) {
        int v = off[i] + bsum[i >> 10];
        off[i] = v;
        cur[i] = v;
    }
    if (i == 0) off[n] = total;
}

__global__ void scatter_csr(const int* __restrict__ ei, int E, int TE,
                            int* __restrict__ cur, int* __restrict__ csr_src) {
    int i = blockIdx.x * blockDim.x + threadIdx.x;
    if (i >= TE) return;
    int s, d;
    if (i < E) { s = ei[i]; d = ei[E + i]; }
    else       { s = i - E; d = s; }
    int pos = atomicAdd(&cur[d], 1);
    csr_src[pos] = s;
}

// ---------------- TF32 tensor-core dual-output GEMM ----------------
// Output1 (first n1 columns) optionally stored as fp16; output2 fp32.
__device__ __forceinline__ unsigned f2tf32(float f) {
    unsigned r;
    asm("cvt.rna.tf32.f32 %0, %1;" : "=r"(r) : "f"(f));
    return r;
}

__device__ __forceinline__ void mma_tf32(float* d, const unsigned* a, const unsigned* b) {
    asm volatile(
        "mma.sync.aligned.m16n8k8.row.col.f32.tf32.tf32.f32 "
        "{%0,%1,%2,%3}, {%4,%5,%6,%7}, {%8,%9}, {%0,%1,%2,%3};"
        : "+f"(d[0]), "+f"(d[1]), "+f"(d[2]), "+f"(d[3])
        : "r"(a[0]), "r"(a[1]), "r"(a[2]), "r"(a[3]), "r"(b[0]), "r"(b[1]));
}

constexpr int kAStr = 36;
constexpr int kBStr = 136;

template <bool HALF1>
__global__ __launch_bounds__(256)
void gemm_dual_tc(const float* __restrict__ A,
                  const float* __restrict__ B1, const float* __restrict__ bias1,
                  void* __restrict__ Cd1, int n1,
                  const float* __restrict__ B2, const float* __restrict__ bias2,
                  float* __restrict__ Cd2, int n2,
                  int M, int K) {
    __shared__ float As[128 * kAStr];
    __shared__ float Bs[32 * kBStr];

    const int tid  = threadIdx.x;
    const int lane = tid & 31;
    const int wid  = tid >> 5;
    const int wm   = (wid & 3) * 32;
    const int wn   = (wid >> 2) * 64;
    const int row0 = blockIdx.y * 128;
    const int col0 = blockIdx.x * 128;

    float d[2][8][4];
#pragma unroll
    for (int mi = 0; mi < 2; ++mi)
#pragma unroll
        for (int ni = 0; ni < 8; ++ni)
#pragma unroll
            for (int r = 0; r < 4; ++r) d[mi][ni][r] = 0.f;

    const int a_row = tid >> 3;
    const int a_c4  = (tid & 7) * 4;
    const int b_row = tid >> 5;
    const int b_c4  = (tid & 31) * 4;

    for (int k0 = 0; k0 < K; k0 += 32) {
#pragma unroll
        for (int p = 0; p < 4; ++p) {
            int r = p * 32 + a_row;
            float4 v = make_float4(0.f, 0.f, 0.f, 0.f);
            if (row0 + r < M)
                v = *(const float4*)(A + (size_t)(row0 + r) * K + k0 + a_c4);
            float* dst = As + r * kAStr + a_c4;
            dst[0] = __uint_as_float(f2tf32(v.x));
            dst[1] = __uint_as_float(f2tf32(v.y));
            dst[2] = __uint_as_float(f2tf32(v.z));
            dst[3] = __uint_as_float(f2tf32(v.w));
        }
#pragma unroll
        for (int p = 0; p < 4; ++p) {
            int r = p * 8 + b_row;
            int kg = k0 + r;
            int cg = col0 + b_c4;
            float4 v;
            if (cg < n1) v = *(const float4*)(B1 + (size_t)kg * n1 + cg);
            else         v = *(const float4*)(B2 + (size_t)kg * n2 + (cg - n1));
            float* dst = Bs + r * kBStr + b_c4;
            dst[0] = __uint_as_float(f2tf32(v.x));
            dst[1] = __uint_as_float(f2tf32(v.y));
            dst[2] = __uint_as_float(f2tf32(v.z));
            dst[3] = __uint_as_float(f2tf32(v.w));
        }
        __syncthreads();

#pragma unroll
        for (int k8 = 0; k8 < 4; ++k8) {
            unsigned a[2][4], b[8][2];
            const int kk = k8 * 8 + (lane & 3);
            const int gr = lane >> 2;
#pragma unroll
            for (int mi = 0; mi < 2; ++mi) {
                int rbase = wm + mi * 16 + gr;
                a[mi][0] = __float_as_uint(As[rbase * kAStr + kk]);
                a[mi][1] = __float_as_uint(As[(rbase + 8) * kAStr + kk]);
                a[mi][2] = __float_as_uint(As[rbase * kAStr + kk + 4]);
                a[mi][3] = __float_as_uint(As[(rbase + 8) * kAStr + kk + 4]);
            }
#pragma unroll
            for (int ni = 0; ni < 8; ++ni) {
                int c = wn + ni * 8 + gr;
                b[ni][0] = __float_as_uint(Bs[kk * kBStr + c]);
                b[ni][1] = __float_as_uint(Bs[(kk + 4) * kBStr + c]);
            }
#pragma unroll
            for (int mi = 0; mi < 2; ++mi)
#pragma unroll
                for (int ni = 0; ni < 8; ++ni)
                    mma_tf32(d[mi][ni], a[mi], b[ni]);
        }
        __syncthreads();
    }

    const bool isOut1 = (col0 + wn < n1);
    const float* bias = isOut1 ? bias1 : bias2;
    const int Nc      = isOut1 ? n1 : n2;
    const int cbase   = isOut1 ? (col0 + wn) : (col0 + wn - n1);

#pragma unroll
    for (int mi = 0; mi < 2; ++mi) {
#pragma unroll
        for (int half = 0; half < 2; ++half) {
            int r = row0 + wm + mi * 16 + (lane >> 2) + half * 8;
            if (r >= M) continue;
#pragma unroll
            for (int ni = 0; ni < 8; ++ni) {
                int c = cbase + ni * 8 + 2 * (lane & 3);
                float vx = d[mi][ni][half * 2 + 0] + __ldg(bias + c + 0);
                float vy = d[mi][ni][half * 2 + 1] + __ldg(bias + c + 1);
                if (isOut1) {
                    if (HALF1) {
                        __half* Co = (__half*)Cd1;
                        *(__half2*)(Co + (size_t)r * Nc + c) = __floats2half2_rn(vx, vy);
                    } else {
                        float* Co = (float*)Cd1;
                        *(float2*)(Co + (size_t)r * Nc + c) = make_float2(vx, vy);
                    }
                } else {
                    *(float2*)(Cd2 + (size_t)r * Nc + c) = make_float2(vx, vy);
                }
            }
        }
    }
}

// ---------------- helpers ----------------
__device__ __forceinline__ float leaky(float t) { return fmaxf(t, 0.2f * t); }

// ---------------- layer-1 fused edge phase (H=4, C=64, +bias +elu) ----------------
// One warp per dst node. Lane covers cols [lane*8, lane*8+8): entirely in head
// lane>>3. One LDG.128 (8 fp16) per edge per lane; 3-shuffle octet reduce; each
// lane keeps the single (m,s) softmax state of its own head.
__global__ void gat_fused_l1(const int* __restrict__ off, const int* __restrict__ csr,
                             const __half* __restrict__ xl, const float* __restrict__ xr,
                             const float* __restrict__ att, const float* __restrict__ bias,
                             float* __restrict__ out, int N) {
    int node = (blockIdx.x * blockDim.x + threadIdx.x) >> 5;
    if (node >= N) return;
    int lane = threadIdx.x & 31;

    const float4* prx = (const float4*)(xr + (size_t)node * 256);
    float4 xra = __ldg(prx + lane * 2);
    float4 xrb = __ldg(prx + lane * 2 + 1);
    const float4* pat = (const float4*)att;
    float4 ata = __ldg(pat + lane * 2);
    float4 atb = __ldg(pat + lane * 2 + 1);

    float acc[8];
#pragma unroll
    for (int i = 0; i < 8; ++i) acc[i] = 0.f;
    float m = -1e30f, s = 0.f;

    int e0 = __ldg(off + node), e1 = __ldg(off + node + 1);
#pragma unroll 2
    for (int e = e0; e < e1; ++e) {
        int src = __ldg(csr + e);
        uint4 u = __ldg((const uint4*)(xl + (size_t)src * 256) + lane);
        const __half2* hp = (const __half2*)&u;
        float2 f0 = __half22float2(hp[0]);
        float2 f1 = __half22float2(hp[1]);
        float2 f2 = __half22float2(hp[2]);
        float2 f3 = __half22float2(hp[3]);
        float v[8] = {f0.x, f0.y, f1.x, f1.y, f2.x, f2.y, f3.x, f3.y};

        float q = leaky(v[0] + xra.x) * ata.x;
        q = fmaf(leaky(v[1] + xra.y), ata.y, q);
        q = fmaf(leaky(v[2] + xra.z), ata.z, q);
        q = fmaf(leaky(v[3] + xra.w), ata.w, q);
        q = fmaf(leaky(v[4] + xrb.x), atb.x, q);
        q = fmaf(leaky(v[5] + xrb.y), atb.y, q);
        q = fmaf(leaky(v[6] + xrb.z), atb.z, q);
        q = fmaf(leaky(v[7] + xrb.w), atb.w, q);

        // octet reduce (8 lanes per head)
        q += __shfl_xor_sync(0xffffffffu, q, 4);
        q += __shfl_xor_sync(0xffffffffu, q, 2);
        q += __shfl_xor_sync(0xffffffffu, q, 1);

        // branchless online softmax (single head per lane)
        float nm = fmaxf(m, q);
        float sc = __expf(m - nm);
        float w  = __expf(q - nm);
        s = s * sc + w;
        m = nm;
#pragma unroll
        for (int i = 0; i < 8; ++i) acc[i] = fmaf(acc[i], sc, w * v[i]);
    }

    float inv = 1.f / s;
    const float4* pb = (const float4*)bias;
    float4 b0 = __ldg(pb + lane * 2), b1 = __ldg(pb + lane * 2 + 1);
    float o[8];
    o[0] = acc[0] * inv + b0.x;  o[1] = acc[1] * inv + b0.y;
    o[2] = acc[2] * inv + b0.z;  o[3] = acc[3] * inv + b0.w;
    o[4] = acc[4] * inv + b1.x;  o[5] = acc[5] * inv + b1.y;
    o[6] = acc[6] * inv + b1.z;  o[7] = acc[7] * inv + b1.w;
#pragma unroll
    for (int i = 0; i < 8; ++i) o[i] = (o[i] > 0.f) ? o[i] : expm1f(o[i]);

    float4* po = (float4*)(out + (size_t)node * 256);
    po[lane * 2]     = make_float4(o[0], o[1], o[2], o[3]);
    po[lane * 2 + 1] = make_float4(o[4], o[5], o[6], o[7]);
}

// ---------------- layer-2 fused edge phase (H=1, C=64, +bias) ----------------
__global__ void gat_fused_l2(const int* __restrict__ off, const int* __restrict__ csr,
                             const __half* __restrict__ xl, const float* __restrict__ xr,
                             const float* __restrict__ att, const float* __restrict__ bias,
                             float* __restrict__ out, int N) {
    int node = (blockIdx.x * blockDim.x + threadIdx.x) >> 5;
    if (node >= N) return;
    int lane = threadIdx.x & 31;

    float2 xrv = __ldg((const float2*)(xr + (size_t)node * 64) + lane);
    float2 atv = __ldg((const float2*)att + lane);

    float2 acc = make_float2(0.f, 0.f);
    float m = -1e30f, s = 0.f;

    int e0 = __ldg(off + node), e1 = __ldg(off + node + 1);
#pragma unroll 2
    for (int e = e0; e < e1; ++e) {
        int src = __ldg(csr + e);
        __half2 hv = __ldg((const __half2*)(xl + (size_t)src * 64) + lane);
        float2 v = __half22float2(hv);
        float q = leaky(v.x + xrv.x) * atv.x;
        q = fmaf(leaky(v.y + xrv.y), atv.y, q);
#pragma unroll
        for (int o = 16; o; o >>= 1) q += __shfl_xor_sync(0xffffffffu, q, o);
        float nm = fmaxf(m, q);
        float sc = __expf(m - nm);
        float w  = __expf(q - nm);
        s = s * sc + w;
        m = nm;
        acc.x = fmaf(acc.x, sc, w * v.x);
        acc.y = fmaf(acc.y, sc, w * v.y);
    }

    float inv = 1.f / s;
    float2 bv = __ldg((const float2*)bias + lane);
    float2 o;
    o.x = acc.x * inv + bv.x;
    o.y = acc.y * inv + bv.y;
    *((float2*)(out + (size_t)node * 64) + lane) = o;
}

// ---------------- host launch ----------------
static __half* p_xl1 = nullptr;
static float*  p_xr1 = nullptr;
static float*  p_h   = nullptr;
static __half* p_xl2 = nullptr;
static float*  p_xr2 = nullptr;
static int*    p_deg = nullptr;
static int*    p_off = nullptr;
static int*    p_cur = nullptr;
static int*    p_bsum = nullptr;
static int*    p_csr = nullptr;
static cudaStream_t s_side = nullptr;
static cudaEvent_t  s_fork = nullptr, s_join = nullptr;

extern "C" void kernel_launch(void* const* d_in, const int* in_sizes, int n_in,
                              void* d_out, int out_size) {
    if (!p_xl1) {
        void* p;
        cudaGetSymbolAddress(&p, g_xl1);     p_xl1 = (__half*)p;
        cudaGetSymbolAddress(&p, g_xr1);     p_xr1 = (float*)p;
        cudaGetSymbolAddress(&p, g_h);       p_h   = (float*)p;
        cudaGetSymbolAddress(&p, g_xl2);     p_xl2 = (__half*)p;
        cudaGetSymbolAddress(&p, g_xr2);     p_xr2 = (float*)p;
        cudaGetSymbolAddress(&p, g_deg);     p_deg = (int*)p;
        cudaGetSymbolAddress(&p, g_off);     p_off = (int*)p;
        cudaGetSymbolAddress(&p, g_cur);     p_cur = (int*)p;
        cudaGetSymbolAddress(&p, g_bsum);    p_bsum = (int*)p;
        cudaGetSymbolAddress(&p, g_csr_src); p_csr = (int*)p;
        cudaStreamCreateWithFlags(&s_side, cudaStreamNonBlocking);
        cudaEventCreateWithFlags(&s_fork, cudaEventDisableTiming);
        cudaEventCreateWithFlags(&s_join, cudaEventDisableTiming);
    }

    const float* x     = (const float*)d_in[0];
    const int*   ei    = (const int*)d_in[1];
    const float* Wl1   = (const float*)d_in[2];
    const float* bl1   = (const float*)d_in[3];
    const float* Wr1   = (const float*)d_in[4];
    const float* br1   = (const float*)d_in[5];
    const float* att1  = (const float*)d_in[6];
    const float* bias1 = (const float*)d_in[7];
    const float* Wl2   = (const float*)d_in[8];
    const float* bl2   = (const float*)d_in[9];
    const float* Wr2   = (const float*)d_in[10];
    const float* br2   = (const float*)d_in[11];
    const float* att2  = (const float*)d_in[12];
    const float* bias2 = (const float*)d_in[13];
    float* out = (float*)d_out;

    const int IN = 128;
    const int N  = in_sizes[0] / IN;
    const int E  = in_sizes[1] / 2;
    const int TE = E + N;

    const int T = 256;
    auto cdiv = [](int a, int b) { return (a + b - 1) / b; };

    // ---- fork: CSR build on side stream, concurrent with layer-1 GEMM ----
    cudaEventRecord(s_fork, 0);
    cudaStreamWaitEvent(s_side, s_fork, 0);

    zeroi<<<cdiv(N, T), T, 0, s_side>>>(p_deg, N);
    count_deg<<<cdiv(TE, T), T, 0, s_side>>>(ei, E, TE, p_deg);
    int nb = cdiv(N, 1024);
    scan_block<<<nb, 1024, 0, s_side>>>(p_deg, p_off, p_bsum, N);
    scan_sums<<<1, 128, 0, s_side>>>(p_bsum, nb);
    scan_add<<<cdiv(N, T), T, 0, s_side>>>(p_off, p_bsum, p_cur, N, TE);
    scatter_csr<<<cdiv(TE, T), T, 0, s_side>>>(ei, E, TE, p_cur, p_csr);
    cudaEventRecord(s_join, s_side);

    // ---- layer 1 GEMM: xl1 (fp16) | xr1 (fp32) ----
    {
        dim3 grid((kHC1 + kHC1) / 128, cdiv(N, 128));
        gemm_dual_tc<true><<<grid, 256>>>(x, Wl1, bl1, (void*)p_xl1, kHC1,
                                          Wr1, br1, p_xr1, kHC1, N, IN);
    }

    // ---- join, then fused edge phase layer 1 ----
    cudaStreamWaitEvent(0, s_join, 0);
    gat_fused_l1<<<cdiv(N * 32, T), T>>>(p_off, p_csr, p_xl1, p_xr1, att1, bias1, p_h, N);

    // ---- layer 2 GEMM: xl2 (fp16) | xr2 (fp32) ----
    {
        dim3 grid((kC2 + kC2) / 128, cdiv(N, 128));
        gemm_dual_tc<true><<<grid, 256>>>(p_h, Wl2, bl2, (void*)p_xl2, kC2,
                                          Wr2, br2, p_xr2, kC2, N, kHC1);
    }
    // ---- layer 2 fused edge phase -> out ----
    gat_fused_l2<<<cdiv(N * 32, T), T>>>(p_off, p_csr, p_xl2, p_xr2, att2, bias2, out, N);
}